// round 2
// baseline (speedup 1.0000x reference)
#include <cuda_runtime.h>
#include <math.h>

#define D_MODEL 1024
#define SEQ     2048
#define BATCH   4
#define NH      16
#define HD      64
#define ROWS    (BATCH * SEQ)   // 8192

// Scratch (device globals — no runtime allocation allowed)
__device__ float g_xln[ROWS * D_MODEL];
__device__ float g_q[ROWS * D_MODEL];
__device__ float g_k[ROWS * D_MODEL];
__device__ float g_v[ROWS * D_MODEL];
__device__ float g_att[ROWS * D_MODEL];
__device__ float g_emb[SEQ * HD];

// ---------------------------------------------------------------------------
// Rotary emb table: emb[s][d] = d<32 ? sin(s*f_d) : cos(s*f_{d-32}),
// f_i = 10000^(-i/32). Computed in double (args up to ~2048 rad).
// ---------------------------------------------------------------------------
__global__ void emb_kernel() {
    int s = blockIdx.x;
    int d = threadIdx.x;            // 0..63
    int i = d & 31;
    double f = exp(-log(10000.0) * (double)i / 32.0);
    double a = (double)s * f;
    g_emb[s * HD + d] = (d < 32) ? (float)sin(a) : (float)cos(a);
}

// ---------------------------------------------------------------------------
// LayerNorm: one block per row (1024 elems, 256 threads x float4)
// ---------------------------------------------------------------------------
__global__ __launch_bounds__(256) void ln_kernel(const float* __restrict__ x,
                                                 const float* __restrict__ g,
                                                 const float* __restrict__ b) {
    int row = blockIdx.x;
    int tid = threadIdx.x;
    const float* xr = x + (size_t)row * D_MODEL;
    float4 v = *(const float4*)(xr + tid * 4);
    float s1 = v.x + v.y + v.z + v.w;
    float s2 = v.x * v.x + v.y * v.y + v.z * v.z + v.w * v.w;
#pragma unroll
    for (int off = 16; off; off >>= 1) {
        s1 += __shfl_xor_sync(0xffffffffu, s1, off);
        s2 += __shfl_xor_sync(0xffffffffu, s2, off);
    }
    __shared__ float r1[8], r2[8];
    int w = tid >> 5, lane = tid & 31;
    if (lane == 0) { r1[w] = s1; r2[w] = s2; }
    __syncthreads();
    float t1 = 0.f, t2 = 0.f;
#pragma unroll
    for (int i = 0; i < 8; i++) { t1 += r1[i]; t2 += r2[i]; }
    float mu   = t1 * (1.f / D_MODEL);
    float var  = t2 * (1.f / D_MODEL) - mu * mu;
    float rstd = rsqrtf(var + 1e-5f);
    float4 gv = *(const float4*)(g + tid * 4);
    float4 bv = *(const float4*)(b + tid * 4);
    float4 o;
    o.x = (v.x - mu) * rstd * gv.x + bv.x;
    o.y = (v.y - mu) * rstd * gv.y + bv.y;
    o.z = (v.z - mu) * rstd * gv.z + bv.z;
    o.w = (v.w - mu) * rstd * gv.w + bv.w;
    *(float4*)&g_xln[(size_t)row * D_MODEL + tid * 4] = o;
}

// ---------------------------------------------------------------------------
// Tiled GEMM: C[M,N] = A[M,K] @ W[N,K]^T  (both row-major), 128x128x16 tiles,
// 256 threads, 8x8 micro-tile per thread (split rows/cols: t*4 and 64+t*4).
// ---------------------------------------------------------------------------
#define GEMM_LOAD_TILES(Aptr, Wptr)                                             \
    {                                                                           \
        _Pragma("unroll")                                                       \
        for (int t = 0; t < 2; t++) {                                           \
            int ff = tid + t * 256;                                             \
            int r = ff >> 2;                                                    \
            int c = (ff & 3) << 2;                                              \
            float4 va = *(const float4*)((Aptr) + (size_t)(row0 + r) * 1024 + kt + c); \
            As[c + 0][r] = va.x; As[c + 1][r] = va.y;                           \
            As[c + 2][r] = va.z; As[c + 3][r] = va.w;                           \
            float4 vb = *(const float4*)((Wptr) + (size_t)(col0 + r) * 1024 + kt + c); \
            Bs[c + 0][r] = vb.x; Bs[c + 1][r] = vb.y;                           \
            Bs[c + 2][r] = vb.z; Bs[c + 3][r] = vb.w;                           \
        }                                                                       \
    }

#define GEMM_COMPUTE()                                                          \
    {                                                                           \
        _Pragma("unroll")                                                       \
        for (int k = 0; k < 16; k++) {                                          \
            float4 t0 = *(const float4*)&As[k][ty * 4];                         \
            float4 t1 = *(const float4*)&As[k][64 + ty * 4];                    \
            float4 t2 = *(const float4*)&Bs[k][tx * 4];                         \
            float4 t3 = *(const float4*)&Bs[k][64 + tx * 4];                    \
            float a[8] = {t0.x, t0.y, t0.z, t0.w, t1.x, t1.y, t1.z, t1.w};     \
            float bb[8] = {t2.x, t2.y, t2.z, t2.w, t3.x, t3.y, t3.z, t3.w};    \
            _Pragma("unroll")                                                   \
            for (int i = 0; i < 8; i++)                                         \
                _Pragma("unroll")                                               \
                for (int j = 0; j < 8; j++) acc[i][j] += a[i] * bb[j];          \
        }                                                                       \
    }

// QKV projection + rotary, scatter to [B,H,S,d]
__global__ __launch_bounds__(256) void gemm_qkv_kernel(const float* __restrict__ Wq,
                                                       const float* __restrict__ Wk,
                                                       const float* __restrict__ Wv) {
    __shared__ float As[16][132];
    __shared__ float Bs[16][132];
    int z = blockIdx.z;
    const float* W = (z == 0) ? Wq : (z == 1) ? Wk : Wv;
    float* dst = (z == 0) ? g_q : (z == 1) ? g_k : g_v;
    int row0 = blockIdx.y * 128;
    int col0 = blockIdx.x * 128;
    int tid = threadIdx.x, tx = tid & 15, ty = tid >> 4;
    float acc[8][8];
#pragma unroll
    for (int i = 0; i < 8; i++)
#pragma unroll
        for (int j = 0; j < 8; j++) acc[i][j] = 0.f;

    for (int kt = 0; kt < 1024; kt += 16) {
        GEMM_LOAD_TILES(g_xln, W);
        __syncthreads();
        GEMM_COMPUTE();
        __syncthreads();
    }
#pragma unroll
    for (int i = 0; i < 8; i++) {
        int r = row0 + (i < 4 ? ty * 4 + i : 64 + ty * 4 + i - 4);
        int bb_ = r >> 11;
        int s = r & 2047;
#pragma unroll
        for (int jg = 0; jg < 2; jg++) {
            int c0 = col0 + (jg ? 64 + tx * 4 : tx * 4);
            int h = c0 >> 6, dd = c0 & 63;
            float4 ov;
            ov.x = acc[i][jg * 4 + 0];
            ov.y = acc[i][jg * 4 + 1];
            ov.z = acc[i][jg * 4 + 2];
            ov.w = acc[i][jg * 4 + 3];
            if (z < 2) {
                float4 e = *(const float4*)&g_emb[s * HD + dd];
                ov.x *= e.x; ov.y *= e.y; ov.z *= e.z; ov.w *= e.w;
            }
            *(float4*)&dst[(size_t)((bb_ * NH + h) * SEQ + s) * HD + dd] = ov;
        }
    }
}

// Output projection + bias + residual -> d_out
__global__ __launch_bounds__(256) void gemm_out_kernel(const float* __restrict__ Wo,
                                                       const float* __restrict__ bias,
                                                       const float* __restrict__ x,
                                                       float* __restrict__ out) {
    __shared__ float As[16][132];
    __shared__ float Bs[16][132];
    int row0 = blockIdx.y * 128;
    int col0 = blockIdx.x * 128;
    int tid = threadIdx.x, tx = tid & 15, ty = tid >> 4;
    float acc[8][8];
#pragma unroll
    for (int i = 0; i < 8; i++)
#pragma unroll
        for (int j = 0; j < 8; j++) acc[i][j] = 0.f;

    for (int kt = 0; kt < 1024; kt += 16) {
        GEMM_LOAD_TILES(g_att, Wo);
        __syncthreads();
        GEMM_COMPUTE();
        __syncthreads();
    }
#pragma unroll
    for (int i = 0; i < 8; i++) {
        int r = row0 + (i < 4 ? ty * 4 + i : 64 + ty * 4 + i - 4);
#pragma unroll
        for (int jg = 0; jg < 2; jg++) {
            int c0 = col0 + (jg ? 64 + tx * 4 : tx * 4);
            float4 bv = *(const float4*)&bias[c0];
            float4 xv = *(const float4*)&x[(size_t)r * 1024 + c0];
            float4 ov;
            ov.x = acc[i][jg * 4 + 0] + bv.x + xv.x;
            ov.y = acc[i][jg * 4 + 1] + bv.y + xv.y;
            ov.z = acc[i][jg * 4 + 2] + bv.z + xv.z;
            ov.w = acc[i][jg * 4 + 3] + bv.w + xv.w;
            *(float4*)&out[(size_t)r * 1024 + c0] = ov;
        }
    }
}

// ---------------------------------------------------------------------------
// Flash attention: 128-query x 64-key tiles, online softmax, causal skipping.
// Block 256 threads (16x16): thread owns 8 rows x 4 dims.
// ---------------------------------------------------------------------------
#define FL_QS   0                       // 128*64
#define FL_KST  (128 * 64)              // 64*65 (transposed, padded)
#define FL_VS   (FL_KST + 64 * 65)      // 64*64
#define FL_PS   (FL_VS + 64 * 64)       // 128*68 (padded)
#define FL_MS   (FL_PS + 128 * 68)      // 64 mask addends
#define FL_WORDS (FL_MS + 64)
#define FL_BYTES (FL_WORDS * 4)

__global__ __launch_bounds__(256, 2) void flash_kernel(const unsigned char* __restrict__ kpm) {
    extern __shared__ float sm[];
    float* Qs  = sm + FL_QS;
    float* KsT = sm + FL_KST;
    float* Vs  = sm + FL_VS;
    float* Ps  = sm + FL_PS;
    float* Ms  = sm + FL_MS;

    int qt = blockIdx.x;      // 0..15
    int bh = blockIdx.y;      // 0..63
    int b = bh >> 4;
    int h = bh & 15;
    int tid = threadIdx.x, tx = tid & 15, ty = tid >> 4;
    int q0 = qt * 128;

    int rl[8];
#pragma unroll
    for (int i = 0; i < 8; i++) rl[i] = (i < 4) ? ty * 4 + i : 64 + ty * 4 + (i - 4);

    // Load Q tile, pre-scale by 1/sqrt(64)
    const float* Qg = g_q + (size_t)(bh * SEQ + q0) * HD;
#pragma unroll
    for (int t = 0; t < 8; t++) {
        int ff = tid + t * 256;             // 2048 float4s
        int r = ff >> 4;
        int c = (ff & 15) << 2;
        float4 v = *(const float4*)(Qg + r * HD + c);
        v.x *= 0.125f; v.y *= 0.125f; v.z *= 0.125f; v.w *= 0.125f;
        *(float4*)&Qs[r * 64 + c] = v;
    }

    float m[8], l[8], o[8][4];
#pragma unroll
    for (int i = 0; i < 8; i++) {
        m[i] = -INFINITY; l[i] = 0.f;
#pragma unroll
        for (int j = 0; j < 4; j++) o[i][j] = 0.f;
    }

    int ktmax = (q0 + 127) >> 6;            // inclusive
    for (int kt = 0; kt <= ktmax; kt++) {
        int k0 = kt * 64;
        const float* Kg = g_k + (size_t)(bh * SEQ + k0) * HD;
        const float* Vg = g_v + (size_t)(bh * SEQ + k0) * HD;
#pragma unroll
        for (int t = 0; t < 4; t++) {
            int ff = tid + t * 256;         // 1024 float4s
            int r = ff >> 4;
            int c = (ff & 15) << 2;
            float4 kv = *(const float4*)(Kg + r * HD + c);
            KsT[(c + 0) * 65 + r] = kv.x;
            KsT[(c + 1) * 65 + r] = kv.y;
            KsT[(c + 2) * 65 + r] = kv.z;
            KsT[(c + 3) * 65 + r] = kv.w;
            float4 vv = *(const float4*)(Vg + r * HD + c);
            *(float4*)&Vs[r * 64 + c] = vv;
        }
        if (tid < 64) Ms[tid] = kpm[b * SEQ + k0 + tid] ? -INFINITY : 0.f;
        __syncthreads();

        // S = Q @ K^T
        float s[8][4];
#pragma unroll
        for (int i = 0; i < 8; i++)
#pragma unroll
            for (int j = 0; j < 4; j++) s[i][j] = 0.f;
#pragma unroll 4
        for (int k = 0; k < 64; k++) {
            float kb[4];
#pragma unroll
            for (int j = 0; j < 4; j++) kb[j] = KsT[k * 65 + tx * 4 + j];
#pragma unroll
            for (int i = 0; i < 8; i++) {
                float qa = Qs[rl[i] * 64 + k];
#pragma unroll
                for (int j = 0; j < 4; j++) s[i][j] += qa * kb[j];
            }
        }

        bool need_c = (k0 + 63 > q0);
#pragma unroll
        for (int i = 0; i < 8; i++) {
#pragma unroll
            for (int j = 0; j < 4; j++) {
                float sv = s[i][j] + Ms[tx * 4 + j];
                if (need_c && (k0 + tx * 4 + j > q0 + rl[i])) sv = -INFINITY;
                s[i][j] = sv;
            }
        }

        // Online softmax update
#pragma unroll
        for (int i = 0; i < 8; i++) {
            float mt = fmaxf(fmaxf(s[i][0], s[i][1]), fmaxf(s[i][2], s[i][3]));
#pragma unroll
            for (int off = 8; off; off >>= 1)
                mt = fmaxf(mt, __shfl_xor_sync(0xffffffffu, mt, off));
            float mn = fmaxf(m[i], mt);
            float corr = expf(m[i] - mn);
            float4 pv;
            pv.x = expf(s[i][0] - mn);
            pv.y = expf(s[i][1] - mn);
            pv.z = expf(s[i][2] - mn);
            pv.w = expf(s[i][3] - mn);
            float rs = pv.x + pv.y + pv.z + pv.w;
#pragma unroll
            for (int off = 8; off; off >>= 1)
                rs += __shfl_xor_sync(0xffffffffu, rs, off);
            *(float4*)&Ps[rl[i] * 68 + tx * 4] = pv;
            l[i] = l[i] * corr + rs;
            m[i] = mn;
#pragma unroll
            for (int j = 0; j < 4; j++) o[i][j] *= corr;
        }
        __syncthreads();

        // O += P @ V
#pragma unroll 4
        for (int k = 0; k < 64; k++) {
            float4 vv = *(const float4*)&Vs[k * 64 + tx * 4];
#pragma unroll
            for (int i = 0; i < 8; i++) {
                float pa = Ps[rl[i] * 68 + k];
                o[i][0] += pa * vv.x;
                o[i][1] += pa * vv.y;
                o[i][2] += pa * vv.z;
                o[i][3] += pa * vv.w;
            }
        }
        __syncthreads();
    }

    // Normalize and scatter back to [B,S,D]
#pragma unroll
    for (int i = 0; i < 8; i++) {
        float inv = 1.f / l[i];
        float4 ov;
        ov.x = o[i][0] * inv;
        ov.y = o[i][1] * inv;
        ov.z = o[i][2] * inv;
        ov.w = o[i][3] * inv;
        *(float4*)&g_att[(size_t)(b * SEQ + q0 + rl[i]) * D_MODEL + h * HD + tx * 4] = ov;
    }
}

// ---------------------------------------------------------------------------
extern "C" void kernel_launch(void* const* d_in, const int* in_sizes, int n_in,
                              void* d_out, int out_size) {
    const float* x            = (const float*)d_in[0];
    const unsigned char* kpm  = (const unsigned char*)d_in[1];
    const float* q_w          = (const float*)d_in[2];
    const float* k_w          = (const float*)d_in[3];
    const float* v_w          = (const float*)d_in[4];
    const float* out_w        = (const float*)d_in[5];
    const float* out_b        = (const float*)d_in[6];
    const float* ln_g         = (const float*)d_in[7];
    const float* ln_b         = (const float*)d_in[8];
    float* out = (float*)d_out;

    cudaFuncSetAttribute(flash_kernel, cudaFuncAttributeMaxDynamicSharedMemorySize, FL_BYTES);

    emb_kernel<<<SEQ, HD>>>();
    ln_kernel<<<ROWS, 256>>>(x, ln_g, ln_b);
    gemm_qkv_kernel<<<dim3(8, 64, 3), 256>>>(q_w, k_w, v_w);
    flash_kernel<<<dim3(16, 64), 256, FL_BYTES>>>(kpm);
    gemm_out_kernel<<<dim3(8, 64), 256>>>(out_w, out_b, x, out);
}

// round 9
// speedup vs baseline: 1.3925x; 1.3925x over previous
#include <cuda_runtime.h>
#include <cuda_bf16.h>
#include <math.h>
#include <cstdint>

#define D_MODEL 1024
#define SEQ     2048
#define BATCH   4
#define NH      16
#define HD      64
#define ROWS    (BATCH * SEQ)   // 8192

// ---------------------------------------------------------------------------
// Device-global scratch (no runtime allocation allowed)
// ---------------------------------------------------------------------------
__device__ float g_q[ROWS * D_MODEL];
__device__ float g_k[ROWS * D_MODEL];
__device__ float g_v[ROWS * D_MODEL];
__device__ float g_emb[SEQ * HD];
__device__ __nv_bfloat16 g_xh[ROWS * D_MODEL];   // ln(x) hi
__device__ __nv_bfloat16 g_xl[ROWS * D_MODEL];   // ln(x) lo
__device__ __nv_bfloat16 g_ah[ROWS * D_MODEL];   // attention out hi
__device__ __nv_bfloat16 g_al[ROWS * D_MODEL];   // attention out lo
__device__ __nv_bfloat16 g_wh[4 * D_MODEL * D_MODEL];  // q,k,v,out weights hi
__device__ __nv_bfloat16 g_wl[4 * D_MODEL * D_MODEL];  // lo

// ---------------------------------------------------------------------------
// PTX helpers: ldmatrix / mma.sync bf16 / cp.async (all baseline sm_80+ ISA)
// ---------------------------------------------------------------------------
__device__ __forceinline__ uint32_t smem_to_u32(const void* smem_ptr) {
    uint32_t addr;
    asm("{ .reg .u64 tmp; cvta.to.shared.u64 tmp, %1; cvt.u32.u64 %0, tmp; }"
        : "=r"(addr) : "l"(smem_ptr));
    return addr;
}
__device__ __forceinline__ void ldm_x4(uint32_t* r, uint32_t addr) {
    asm volatile("ldmatrix.sync.aligned.m8n8.x4.shared.b16 {%0,%1,%2,%3}, [%4];"
        : "=r"(r[0]), "=r"(r[1]), "=r"(r[2]), "=r"(r[3]) : "r"(addr));
}
__device__ __forceinline__ void mma_bf16(float* c, const uint32_t* a, const uint32_t* b) {
    asm volatile(
        "mma.sync.aligned.m16n8k16.row.col.f32.bf16.bf16.f32 "
        "{%0,%1,%2,%3}, {%4,%5,%6,%7}, {%8,%9}, {%0,%1,%2,%3};"
        : "+f"(c[0]), "+f"(c[1]), "+f"(c[2]), "+f"(c[3])
        : "r"(a[0]), "r"(a[1]), "r"(a[2]), "r"(a[3]), "r"(b[0]), "r"(b[1]));
}
__device__ __forceinline__ void cp_async16(uint32_t smem, const void* gptr) {
    asm volatile("cp.async.cg.shared.global [%0], [%1], 16;"
        :: "r"(smem), "l"(gptr));
}
#define CP_COMMIT() asm volatile("cp.async.commit_group;" ::: "memory")
#define CP_WAIT1()  asm volatile("cp.async.wait_group 1;" ::: "memory")
#define CP_WAIT0()  asm volatile("cp.async.wait_group 0;" ::: "memory")

// ---------------------------------------------------------------------------
// Rotary emb table (double precision — args reach ~2048 rad)
// ---------------------------------------------------------------------------
__global__ void emb_kernel() {
    int s = blockIdx.x;
    int d = threadIdx.x;            // 0..63
    int i = d & 31;
    double f = exp(-log(10000.0) * (double)i / 32.0);
    double a = (double)s * f;
    g_emb[s * HD + d] = (d < 32) ? (float)sin(a) : (float)cos(a);
}

// ---------------------------------------------------------------------------
// Weight hi/lo bf16 split: 4 x 1024x1024
// ---------------------------------------------------------------------------
__global__ __launch_bounds__(256) void wconv_kernel(const float* __restrict__ q,
                                                    const float* __restrict__ k,
                                                    const float* __restrict__ v,
                                                    const float* __restrict__ o) {
    int i = blockIdx.x * 256 + threadIdx.x;   // 0 .. 4M-1
    int m = i >> 20;
    const float* src = (m == 0) ? q : (m == 1) ? k : (m == 2) ? v : o;
    float val = src[i & 0xFFFFF];
    __nv_bfloat16 h = __float2bfloat16(val);
    g_wh[i] = h;
    g_wl[i] = __float2bfloat16(val - __bfloat162float(h));
}

// ---------------------------------------------------------------------------
// LayerNorm fused with bf16 hi/lo split output
// ---------------------------------------------------------------------------
__global__ __launch_bounds__(256) void ln_kernel(const float* __restrict__ x,
                                                 const float* __restrict__ g,
                                                 const float* __restrict__ b) {
    int row = blockIdx.x;
    int tid = threadIdx.x;
    const float* xr = x + (size_t)row * D_MODEL;
    float4 v = *(const float4*)(xr + tid * 4);
    float s1 = v.x + v.y + v.z + v.w;
    float s2 = v.x * v.x + v.y * v.y + v.z * v.z + v.w * v.w;
#pragma unroll
    for (int off = 16; off; off >>= 1) {
        s1 += __shfl_xor_sync(0xffffffffu, s1, off);
        s2 += __shfl_xor_sync(0xffffffffu, s2, off);
    }
    __shared__ float r1[8], r2[8];
    int w = tid >> 5, lane = tid & 31;
    if (lane == 0) { r1[w] = s1; r2[w] = s2; }
    __syncthreads();
    float t1 = 0.f, t2 = 0.f;
#pragma unroll
    for (int i = 0; i < 8; i++) { t1 += r1[i]; t2 += r2[i]; }
    float mu   = t1 * (1.f / D_MODEL);
    float var  = t2 * (1.f / D_MODEL) - mu * mu;
    float rstd = rsqrtf(var + 1e-5f);
    float4 gv = *(const float4*)(g + tid * 4);
    float4 bv = *(const float4*)(b + tid * 4);
    float o0 = (v.x - mu) * rstd * gv.x + bv.x;
    float o1 = (v.y - mu) * rstd * gv.y + bv.y;
    float o2 = (v.z - mu) * rstd * gv.z + bv.z;
    float o3 = (v.w - mu) * rstd * gv.w + bv.w;
    size_t base = (size_t)row * D_MODEL + tid * 4;
    __nv_bfloat16 h0 = __float2bfloat16(o0), h1 = __float2bfloat16(o1);
    __nv_bfloat16 h2 = __float2bfloat16(o2), h3 = __float2bfloat16(o3);
    *(__nv_bfloat162*)&g_xh[base]     = __nv_bfloat162(h0, h1);
    *(__nv_bfloat162*)&g_xh[base + 2] = __nv_bfloat162(h2, h3);
    *(__nv_bfloat162*)&g_xl[base] =
        __nv_bfloat162(__float2bfloat16(o0 - __bfloat162float(h0)),
                       __float2bfloat16(o1 - __bfloat162float(h1)));
    *(__nv_bfloat162*)&g_xl[base + 2] =
        __nv_bfloat162(__float2bfloat16(o2 - __bfloat162float(h2)),
                       __float2bfloat16(o3 - __bfloat162float(h3)));
}

// ---------------------------------------------------------------------------
// HMMA bf16-split GEMM:  C[128x128 tile] = A[M,1024] @ W[N,1024]^T
//   A = Ah + Al, W = Wh + Wl; C = Ah*Wh + Ah*Wl + Al*Wh  (fp32 accum)
// 256 threads = 8 warps (2x4), warp tile 64x32, BK=32, cp.async double buffer.
// Both A (M x K) and W (N x K) are k-contiguous => BOTH use non-trans ldmatrix
// for row.col mma fragments.
// mode 0: QKV (blockIdx.z picks weight & dst; rotary epilogue, scatter BHSd)
// mode 1: out-proj (bias + residual epilogue -> d_out)
// ---------------------------------------------------------------------------
#define BM 128
#define BN 128
#define BK 32
#define ROWB 80                          // padded smem row bytes (32 bf16 + pad)
#define MAT_BYTES (128 * ROWB)           // 10240
#define BUF_BYTES (4 * MAT_BYTES)        // Ah, Al, Wh, Wl
#define GEMM_SMEM (2 * BUF_BYTES)        // 81920

__global__ __launch_bounds__(256) void mma_gemm_kernel(int mode,
                                                       const float* __restrict__ bias,
                                                       const float* __restrict__ xres,
                                                       float* __restrict__ outp) {
    extern __shared__ char dsm[];
    uint32_t s0 = smem_to_u32(dsm);
    int tid = threadIdx.x, lane = tid & 31, wid = tid >> 5;
    int wm = wid >> 2, wn = wid & 3;
    int z = blockIdx.z;
    int row0 = blockIdx.y * BM;
    int col0 = blockIdx.x * BN;

    const __nv_bfloat16* Ah = (mode == 0) ? g_xh : g_ah;
    const __nv_bfloat16* Al = (mode == 0) ? g_xl : g_al;
    int widx = (mode == 0) ? z : 3;
    const __nv_bfloat16* Wh = g_wh + (size_t)widx * D_MODEL * D_MODEL;
    const __nv_bfloat16* Wl = g_wl + (size_t)widx * D_MODEL * D_MODEL;

    const __nv_bfloat16* srcs[4] = {Ah, Al, Wh, Wl};
    int rbase[4] = {row0, row0, col0, col0};

    float C[4][4][4];
#pragma unroll
    for (int mi = 0; mi < 4; mi++)
#pragma unroll
        for (int nj = 0; nj < 4; nj++)
#pragma unroll
            for (int q = 0; q < 4; q++) C[mi][nj][q] = 0.f;

    auto load_chunk = [&](int c, int bi) {
        int kt = c * BK;
        uint32_t sb = s0 + bi * BUF_BYTES;
#pragma unroll
        for (int m = 0; m < 4; m++) {
            const __nv_bfloat16* src = srcs[m];
            int rb = rbase[m];
#pragma unroll
            for (int rep = 0; rep < 2; rep++) {
                int u = tid + rep * 256;      // 0..511
                int r = u >> 2, cu = u & 3;
                cp_async16(sb + m * MAT_BYTES + r * ROWB + cu * 16,
                           src + (size_t)(rb + r) * D_MODEL + kt + cu * 8);
            }
        }
    };

    // ldmatrix lane addressing (non-trans for both A and B):
    // x4 matrices: mat0 = rows 0-7 @ k-unit 0, mat1 = rows 8-15 @ k-unit 0,
    //              mat2 = rows 0-7 @ k-unit 1, mat3 = rows 8-15 @ k-unit 1
    int amat = lane >> 3;                       // 0..3
    int mrow = (amat & 1) * 8 + (lane & 7);     // row offset within 16-row tile
    int mcu  = amat >> 1;                       // k-unit (16B) offset

    load_chunk(0, 0);
    CP_COMMIT();

    for (int c = 0; c < 32; c++) {
        int bi = c & 1;
        if (c < 32 - 1) { load_chunk(c + 1, bi ^ 1); CP_COMMIT(); CP_WAIT1(); }
        else            { CP_WAIT0(); }
        __syncthreads();

        uint32_t ahB = s0 + bi * BUF_BYTES;
        uint32_t alB = ahB + MAT_BYTES;
        uint32_t whB = ahB + 2 * MAT_BYTES;
        uint32_t wlB = ahB + 3 * MAT_BYTES;

#pragma unroll
        for (int ks = 0; ks < 2; ks++) {
            int k0u = ks * 2;
            uint32_t fa_h[4][4], fa_l[4][4];
#pragma unroll
            for (int mi = 0; mi < 4; mi++) {
                uint32_t off = (uint32_t)((wm * 64 + mi * 16 + mrow) * ROWB +
                                          (k0u + mcu) * 16);
                ldm_x4(fa_h[mi], ahB + off);
                ldm_x4(fa_l[mi], alB + off);
            }
            // B: two 16-row (n) groups cover warp's 32 columns.
            // regs r0,r1 = (n 0-7, k0),(n 0-7, k1); r2,r3 = (n 8-15, k0),(n 8-15, k1)
            uint32_t fb_h[2][4], fb_l[2][4];
#pragma unroll
            for (int hf = 0; hf < 2; hf++) {
                uint32_t off = (uint32_t)((wn * 32 + hf * 16 + mrow) * ROWB +
                                          (k0u + mcu) * 16);
                ldm_x4(fb_h[hf], whB + off);
                ldm_x4(fb_l[hf], wlB + off);
            }
            // fragment regs per mat: mat0=(n0-7,k0) -> b0 ; mat2=(n0-7,k1) -> b1
            //                        mat1=(n8-15,k0)-> b0 ; mat3=(n8-15,k1)-> b1
#pragma unroll
            for (int mi = 0; mi < 4; mi++)
#pragma unroll
                for (int nj = 0; nj < 4; nj++) {
                    int hf = nj >> 1;          // which 16-n group
                    int lo = nj & 1;           // which 8-n half within group
                    uint32_t bh[2], bl[2];
                    bh[0] = fb_h[hf][lo];      // k-unit 0 (mat0/mat1)
                    bh[1] = fb_h[hf][lo + 2];  // k-unit 1 (mat2/mat3)
                    bl[0] = fb_l[hf][lo];
                    bl[1] = fb_l[hf][lo + 2];
                    mma_bf16(C[mi][nj], fa_h[mi], bh);
                    mma_bf16(C[mi][nj], fa_h[mi], bl);
                    mma_bf16(C[mi][nj], fa_l[mi], bh);
                }
        }
        __syncthreads();
    }

    // Epilogue
    int g = lane >> 2, t = lane & 3;
#pragma unroll
    for (int mi = 0; mi < 4; mi++) {
#pragma unroll
        for (int nj = 0; nj < 4; nj++) {
            int cbase = col0 + wn * 32 + nj * 8 + t * 2;
#pragma unroll
            for (int rr = 0; rr < 2; rr++) {
                int r = row0 + wm * 64 + mi * 16 + g + rr * 8;
                float2 v;
                v.x = C[mi][nj][rr * 2 + 0];
                v.y = C[mi][nj][rr * 2 + 1];
                if (mode == 0) {
                    int b = r >> 11, s = r & 2047, h = cbase >> 6, dd = cbase & 63;
                    if (z < 2) {
                        v.x *= g_emb[s * HD + dd];
                        v.y *= g_emb[s * HD + dd + 1];
                    }
                    float* dstm = (z == 0) ? g_q : (z == 1) ? g_k : g_v;
                    *(float2*)&dstm[((size_t)(b * NH + h) * SEQ + s) * HD + dd] = v;
                } else {
                    float2 bv = *(const float2*)&bias[cbase];
                    float2 xv = *(const float2*)&xres[(size_t)r * D_MODEL + cbase];
                    v.x += bv.x + xv.x;
                    v.y += bv.y + xv.y;
                    *(float2*)&outp[(size_t)r * D_MODEL + cbase] = v;
                }
            }
        }
    }
}

// ---------------------------------------------------------------------------
// Flash attention (fp32 FFMA, identical math to the round-2 passing kernel;
// epilogue additionally writes bf16 hi/lo for the out-proj MMA)
// ---------------------------------------------------------------------------
#define FL_QS   0                       // 128*64
#define FL_KST  (128 * 64)              // 64*65 (transposed, padded)
#define FL_VS   (FL_KST + 64 * 65)      // 64*64
#define FL_PS   (FL_VS + 64 * 64)       // 128*68 (padded)
#define FL_MS   (FL_PS + 128 * 68)      // 64 mask addends
#define FL_WORDS (FL_MS + 64)
#define FL_BYTES (FL_WORDS * 4)

__global__ __launch_bounds__(256, 2) void flash_kernel(const unsigned char* __restrict__ kpm) {
    extern __shared__ float sm[];
    float* Qs  = sm + FL_QS;
    float* KsT = sm + FL_KST;
    float* Vs  = sm + FL_VS;
    float* Ps  = sm + FL_PS;
    float* Ms  = sm + FL_MS;

    int qt = blockIdx.x;      // 0..15
    int bh = blockIdx.y;      // 0..63
    int b = bh >> 4;
    int h = bh & 15;
    int tid = threadIdx.x, tx = tid & 15, ty = tid >> 4;
    int q0 = qt * 128;

    int rl[8];
#pragma unroll
    for (int i = 0; i < 8; i++) rl[i] = (i < 4) ? ty * 4 + i : 64 + ty * 4 + (i - 4);

    const float* Qg = g_q + (size_t)(bh * SEQ + q0) * HD;
#pragma unroll
    for (int t = 0; t < 8; t++) {
        int ff = tid + t * 256;
        int r = ff >> 4;
        int c = (ff & 15) << 2;
        float4 v = *(const float4*)(Qg + r * HD + c);
        v.x *= 0.125f; v.y *= 0.125f; v.z *= 0.125f; v.w *= 0.125f;
        *(float4*)&Qs[r * 64 + c] = v;
    }

    float m[8], l[8], o[8][4];
#pragma unroll
    for (int i = 0; i < 8; i++) {
        m[i] = -INFINITY; l[i] = 0.f;
#pragma unroll
        for (int j = 0; j < 4; j++) o[i][j] = 0.f;
    }

    int ktmax = (q0 + 127) >> 6;
    for (int kt = 0; kt <= ktmax; kt++) {
        int k0 = kt * 64;
        const float* Kg = g_k + (size_t)(bh * SEQ + k0) * HD;
        const float* Vg = g_v + (size_t)(bh * SEQ + k0) * HD;
#pragma unroll
        for (int t = 0; t < 4; t++) {
            int ff = tid + t * 256;
            int r = ff >> 4;
            int c = (ff & 15) << 2;
            float4 kv = *(const float4*)(Kg + r * HD + c);
            KsT[(c + 0) * 65 + r] = kv.x;
            KsT[(c + 1) * 65 + r] = kv.y;
            KsT[(c + 2) * 65 + r] = kv.z;
            KsT[(c + 3) * 65 + r] = kv.w;
            float4 vv = *(const float4*)(Vg + r * HD + c);
            *(float4*)&Vs[r * 64 + c] = vv;
        }
        if (tid < 64) Ms[tid] = kpm[b * SEQ + k0 + tid] ? -INFINITY : 0.f;
        __syncthreads();

        float s[8][4];
#pragma unroll
        for (int i = 0; i < 8; i++)
#pragma unroll
            for (int j = 0; j < 4; j++) s[i][j] = 0.f;
#pragma unroll 4
        for (int k = 0; k < 64; k++) {
            float kb[4];
#pragma unroll
            for (int j = 0; j < 4; j++) kb[j] = KsT[k * 65 + tx * 4 + j];
#pragma unroll
            for (int i = 0; i < 8; i++) {
                float qa = Qs[rl[i] * 64 + k];
#pragma unroll
                for (int j = 0; j < 4; j++) s[i][j] += qa * kb[j];
            }
        }

        bool need_c = (k0 + 63 > q0);
#pragma unroll
        for (int i = 0; i < 8; i++) {
#pragma unroll
            for (int j = 0; j < 4; j++) {
                float sv = s[i][j] + Ms[tx * 4 + j];
                if (need_c && (k0 + tx * 4 + j > q0 + rl[i])) sv = -INFINITY;
                s[i][j] = sv;
            }
        }

#pragma unroll
        for (int i = 0; i < 8; i++) {
            float mt = fmaxf(fmaxf(s[i][0], s[i][1]), fmaxf(s[i][2], s[i][3]));
#pragma unroll
            for (int off = 8; off; off >>= 1)
                mt = fmaxf(mt, __shfl_xor_sync(0xffffffffu, mt, off));
            float mn = fmaxf(m[i], mt);
            float corr = expf(m[i] - mn);
            float4 pv;
            pv.x = expf(s[i][0] - mn);
            pv.y = expf(s[i][1] - mn);
            pv.z = expf(s[i][2] - mn);
            pv.w = expf(s[i][3] - mn);
            float rs = pv.x + pv.y + pv.z + pv.w;
#pragma unroll
            for (int off = 8; off; off >>= 1)
                rs += __shfl_xor_sync(0xffffffffu, rs, off);
            *(float4*)&Ps[rl[i] * 68 + tx * 4] = pv;
            l[i] = l[i] * corr + rs;
            m[i] = mn;
#pragma unroll
            for (int j = 0; j < 4; j++) o[i][j] *= corr;
        }
        __syncthreads();

#pragma unroll 4
        for (int k = 0; k < 64; k++) {
            float4 vv = *(const float4*)&Vs[k * 64 + tx * 4];
#pragma unroll
            for (int i = 0; i < 8; i++) {
                float pa = Ps[rl[i] * 68 + k];
                o[i][0] += pa * vv.x;
                o[i][1] += pa * vv.y;
                o[i][2] += pa * vv.z;
                o[i][3] += pa * vv.w;
            }
        }
        __syncthreads();
    }

    // Normalize and write bf16 hi/lo to [B,S,D] layout for out-proj MMA
#pragma unroll
    for (int i = 0; i < 8; i++) {
        float inv = 1.f / l[i];
        float v0 = o[i][0] * inv;
        float v1 = o[i][1] * inv;
        float v2 = o[i][2] * inv;
        float v3 = o[i][3] * inv;
        size_t idx = (size_t)(b * SEQ + q0 + rl[i]) * D_MODEL + h * HD + tx * 4;
        __nv_bfloat16 h0 = __float2bfloat16(v0), h1 = __float2bfloat16(v1);
        __nv_bfloat16 h2 = __float2bfloat16(v2), h3 = __float2bfloat16(v3);
        *(__nv_bfloat162*)&g_ah[idx]     = __nv_bfloat162(h0, h1);
        *(__nv_bfloat162*)&g_ah[idx + 2] = __nv_bfloat162(h2, h3);
        *(__nv_bfloat162*)&g_al[idx] =
            __nv_bfloat162(__float2bfloat16(v0 - __bfloat162float(h0)),
                           __float2bfloat16(v1 - __bfloat162float(h1)));
        *(__nv_bfloat162*)&g_al[idx + 2] =
            __nv_bfloat162(__float2bfloat16(v2 - __bfloat162float(h2)),
                           __float2bfloat16(v3 - __bfloat162float(h3)));
    }
}

// ---------------------------------------------------------------------------
extern "C" void kernel_launch(void* const* d_in, const int* in_sizes, int n_in,
                              void* d_out, int out_size) {
    const float* x            = (const float*)d_in[0];
    const unsigned char* kpm  = (const unsigned char*)d_in[1];
    const float* q_w          = (const float*)d_in[2];
    const float* k_w          = (const float*)d_in[3];
    const float* v_w          = (const float*)d_in[4];
    const float* out_w        = (const float*)d_in[5];
    const float* out_b        = (const float*)d_in[6];
    const float* ln_g         = (const float*)d_in[7];
    const float* ln_b         = (const float*)d_in[8];
    float* out = (float*)d_out;

    cudaFuncSetAttribute(flash_kernel, cudaFuncAttributeMaxDynamicSharedMemorySize, FL_BYTES);
    cudaFuncSetAttribute(mma_gemm_kernel, cudaFuncAttributeMaxDynamicSharedMemorySize, GEMM_SMEM);

    emb_kernel<<<SEQ, HD>>>();
    wconv_kernel<<<(4 * D_MODEL * D_MODEL) / 256, 256>>>(q_w, k_w, v_w, out_w);
    ln_kernel<<<ROWS, 256>>>(x, ln_g, ln_b);
    mma_gemm_kernel<<<dim3(D_MODEL / BN, ROWS / BM, 3), 256, GEMM_SMEM>>>(
        0, nullptr, nullptr, nullptr);
    flash_kernel<<<dim3(16, 64), 256, FL_BYTES>>>(kpm);
    mma_gemm_kernel<<<dim3(D_MODEL / BN, ROWS / BM, 1), 256, GEMM_SMEM>>>(
        1, out_b, x, out);
}

// round 10
// speedup vs baseline: 2.2395x; 1.6082x over previous
#include <cuda_runtime.h>
#include <cuda_bf16.h>
#include <math.h>
#include <cstdint>

#define D_MODEL 1024
#define SEQ     2048
#define BATCH   4
#define NH      16
#define HD      64
#define ROWS    (BATCH * SEQ)   // 8192

// ---------------------------------------------------------------------------
// Device-global scratch (no runtime allocation allowed)
// ---------------------------------------------------------------------------
__device__ float g_emb[SEQ * HD];
__device__ __nv_bfloat16 g_qh[ROWS * D_MODEL];   // Q (rot, pre-scaled) hi  [b,h,s,d]
__device__ __nv_bfloat16 g_ql[ROWS * D_MODEL];   // lo
__device__ __nv_bfloat16 g_kh[ROWS * D_MODEL];   // K (rot) hi             [b,h,s,d]
__device__ __nv_bfloat16 g_kl[ROWS * D_MODEL];   // lo
__device__ __nv_bfloat16 g_vth[ROWS * D_MODEL];  // V hi TRANSPOSED        [b,h,d,s]
__device__ __nv_bfloat16 g_vtl[ROWS * D_MODEL];  // lo
__device__ __nv_bfloat16 g_xh[ROWS * D_MODEL];   // ln(x) hi
__device__ __nv_bfloat16 g_xl[ROWS * D_MODEL];   // ln(x) lo
__device__ __nv_bfloat16 g_ah[ROWS * D_MODEL];   // attention out hi
__device__ __nv_bfloat16 g_al[ROWS * D_MODEL];   // attention out lo
__device__ __nv_bfloat16 g_wh[4 * D_MODEL * D_MODEL];  // q,k,v,out weights hi
__device__ __nv_bfloat16 g_wl[4 * D_MODEL * D_MODEL];  // lo

// ---------------------------------------------------------------------------
// PTX helpers: ldmatrix / mma.sync bf16 / cp.async (all baseline sm_80+ ISA)
// ---------------------------------------------------------------------------
__device__ __forceinline__ uint32_t smem_to_u32(const void* smem_ptr) {
    uint32_t addr;
    asm("{ .reg .u64 tmp; cvta.to.shared.u64 tmp, %1; cvt.u32.u64 %0, tmp; }"
        : "=r"(addr) : "l"(smem_ptr));
    return addr;
}
__device__ __forceinline__ void ldm_x4(uint32_t* r, uint32_t addr) {
    asm volatile("ldmatrix.sync.aligned.m8n8.x4.shared.b16 {%0,%1,%2,%3}, [%4];"
        : "=r"(r[0]), "=r"(r[1]), "=r"(r[2]), "=r"(r[3]) : "r"(addr));
}
__device__ __forceinline__ void mma_bf16(float* c, const uint32_t* a, const uint32_t* b) {
    asm volatile(
        "mma.sync.aligned.m16n8k16.row.col.f32.bf16.bf16.f32 "
        "{%0,%1,%2,%3}, {%4,%5,%6,%7}, {%8,%9}, {%0,%1,%2,%3};"
        : "+f"(c[0]), "+f"(c[1]), "+f"(c[2]), "+f"(c[3])
        : "r"(a[0]), "r"(a[1]), "r"(a[2]), "r"(a[3]), "r"(b[0]), "r"(b[1]));
}
__device__ __forceinline__ void cp_async16(uint32_t smem, const void* gptr) {
    asm volatile("cp.async.cg.shared.global [%0], [%1], 16;"
        :: "r"(smem), "l"(gptr));
}
#define CP_COMMIT() asm volatile("cp.async.commit_group;" ::: "memory")
#define CP_WAIT1()  asm volatile("cp.async.wait_group 1;" ::: "memory")
#define CP_WAIT0()  asm volatile("cp.async.wait_group 0;" ::: "memory")

__device__ __forceinline__ uint32_t pack_bf16x2(float lo, float hi) {
    __nv_bfloat162 p(__float2bfloat16(lo), __float2bfloat16(hi));
    return *(uint32_t*)&p;
}

// ---------------------------------------------------------------------------
// Rotary emb table (double precision — args reach ~2048 rad)
// ---------------------------------------------------------------------------
__global__ void emb_kernel() {
    int s = blockIdx.x;
    int d = threadIdx.x;            // 0..63
    int i = d & 31;
    double f = exp(-log(10000.0) * (double)i / 32.0);
    double a = (double)s * f;
    g_emb[s * HD + d] = (d < 32) ? (float)sin(a) : (float)cos(a);
}

// ---------------------------------------------------------------------------
// Weight hi/lo bf16 split: 4 x 1024x1024
// ---------------------------------------------------------------------------
__global__ __launch_bounds__(256) void wconv_kernel(const float* __restrict__ q,
                                                    const float* __restrict__ k,
                                                    const float* __restrict__ v,
                                                    const float* __restrict__ o) {
    int i = blockIdx.x * 256 + threadIdx.x;   // 0 .. 4M-1
    int m = i >> 20;
    const float* src = (m == 0) ? q : (m == 1) ? k : (m == 2) ? v : o;
    float val = src[i & 0xFFFFF];
    __nv_bfloat16 h = __float2bfloat16(val);
    g_wh[i] = h;
    g_wl[i] = __float2bfloat16(val - __bfloat162float(h));
}

// ---------------------------------------------------------------------------
// LayerNorm fused with bf16 hi/lo split output
// ---------------------------------------------------------------------------
__global__ __launch_bounds__(256) void ln_kernel(const float* __restrict__ x,
                                                 const float* __restrict__ g,
                                                 const float* __restrict__ b) {
    int row = blockIdx.x;
    int tid = threadIdx.x;
    const float* xr = x + (size_t)row * D_MODEL;
    float4 v = *(const float4*)(xr + tid * 4);
    float s1 = v.x + v.y + v.z + v.w;
    float s2 = v.x * v.x + v.y * v.y + v.z * v.z + v.w * v.w;
#pragma unroll
    for (int off = 16; off; off >>= 1) {
        s1 += __shfl_xor_sync(0xffffffffu, s1, off);
        s2 += __shfl_xor_sync(0xffffffffu, s2, off);
    }
    __shared__ float r1[8], r2[8];
    int w = tid >> 5, lane = tid & 31;
    if (lane == 0) { r1[w] = s1; r2[w] = s2; }
    __syncthreads();
    float t1 = 0.f, t2 = 0.f;
#pragma unroll
    for (int i = 0; i < 8; i++) { t1 += r1[i]; t2 += r2[i]; }
    float mu   = t1 * (1.f / D_MODEL);
    float var  = t2 * (1.f / D_MODEL) - mu * mu;
    float rstd = rsqrtf(var + 1e-5f);
    float4 gv = *(const float4*)(g + tid * 4);
    float4 bv = *(const float4*)(b + tid * 4);
    float o0 = (v.x - mu) * rstd * gv.x + bv.x;
    float o1 = (v.y - mu) * rstd * gv.y + bv.y;
    float o2 = (v.z - mu) * rstd * gv.z + bv.z;
    float o3 = (v.w - mu) * rstd * gv.w + bv.w;
    size_t base = (size_t)row * D_MODEL + tid * 4;
    __nv_bfloat16 h0 = __float2bfloat16(o0), h1 = __float2bfloat16(o1);
    __nv_bfloat16 h2 = __float2bfloat16(o2), h3 = __float2bfloat16(o3);
    *(__nv_bfloat162*)&g_xh[base]     = __nv_bfloat162(h0, h1);
    *(__nv_bfloat162*)&g_xh[base + 2] = __nv_bfloat162(h2, h3);
    *(__nv_bfloat162*)&g_xl[base] =
        __nv_bfloat162(__float2bfloat16(o0 - __bfloat162float(h0)),
                       __float2bfloat16(o1 - __bfloat162float(h1)));
    *(__nv_bfloat162*)&g_xl[base + 2] =
        __nv_bfloat162(__float2bfloat16(o2 - __bfloat162float(h2)),
                       __float2bfloat16(o3 - __bfloat162float(h3)));
}

// ---------------------------------------------------------------------------
// HMMA bf16-split GEMM:  C[128x128 tile] = A[M,1024] @ W[N,1024]^T
// (validated round 9). mode 0: QKV -> bf16 hi/lo q/k (+rot, q scaled) and
// transposed v. mode 1: out-proj (bias + residual -> d_out).
// ---------------------------------------------------------------------------
#define BM 128
#define BN 128
#define BK 32
#define ROWB 80                          // padded smem row bytes (32 bf16 + pad)
#define MAT_BYTES (128 * ROWB)           // 10240
#define BUF_BYTES (4 * MAT_BYTES)        // Ah, Al, Wh, Wl
#define GEMM_SMEM (2 * BUF_BYTES)        // 81920

__global__ __launch_bounds__(256) void mma_gemm_kernel(int mode,
                                                       const float* __restrict__ bias,
                                                       const float* __restrict__ xres,
                                                       float* __restrict__ outp) {
    extern __shared__ char dsm[];
    uint32_t s0 = smem_to_u32(dsm);
    int tid = threadIdx.x, lane = tid & 31, wid = tid >> 5;
    int wm = wid >> 2, wn = wid & 3;
    int z = blockIdx.z;
    int row0 = blockIdx.y * BM;
    int col0 = blockIdx.x * BN;

    const __nv_bfloat16* Ah = (mode == 0) ? g_xh : g_ah;
    const __nv_bfloat16* Al = (mode == 0) ? g_xl : g_al;
    int widx = (mode == 0) ? z : 3;
    const __nv_bfloat16* Wh = g_wh + (size_t)widx * D_MODEL * D_MODEL;
    const __nv_bfloat16* Wl = g_wl + (size_t)widx * D_MODEL * D_MODEL;

    const __nv_bfloat16* srcs[4] = {Ah, Al, Wh, Wl};
    int rbase[4] = {row0, row0, col0, col0};

    float C[4][4][4];
#pragma unroll
    for (int mi = 0; mi < 4; mi++)
#pragma unroll
        for (int nj = 0; nj < 4; nj++)
#pragma unroll
            for (int q = 0; q < 4; q++) C[mi][nj][q] = 0.f;

    auto load_chunk = [&](int c, int bi) {
        int kt = c * BK;
        uint32_t sb = s0 + bi * BUF_BYTES;
#pragma unroll
        for (int m = 0; m < 4; m++) {
            const __nv_bfloat16* src = srcs[m];
            int rb = rbase[m];
#pragma unroll
            for (int rep = 0; rep < 2; rep++) {
                int u = tid + rep * 256;      // 0..511
                int r = u >> 2, cu = u & 3;
                cp_async16(sb + m * MAT_BYTES + r * ROWB + cu * 16,
                           src + (size_t)(rb + r) * D_MODEL + kt + cu * 8);
            }
        }
    };

    int amat = lane >> 3;                       // 0..3
    int mrow = (amat & 1) * 8 + (lane & 7);     // row offset within 16-row tile
    int mcu  = amat >> 1;                       // k-unit (16B) offset

    load_chunk(0, 0);
    CP_COMMIT();

    for (int c = 0; c < 32; c++) {
        int bi = c & 1;
        if (c < 32 - 1) { load_chunk(c + 1, bi ^ 1); CP_COMMIT(); CP_WAIT1(); }
        else            { CP_WAIT0(); }
        __syncthreads();

        uint32_t ahB = s0 + bi * BUF_BYTES;
        uint32_t alB = ahB + MAT_BYTES;
        uint32_t whB = ahB + 2 * MAT_BYTES;
        uint32_t wlB = ahB + 3 * MAT_BYTES;

#pragma unroll
        for (int ks = 0; ks < 2; ks++) {
            int k0u = ks * 2;
            uint32_t fa_h[4][4], fa_l[4][4];
#pragma unroll
            for (int mi = 0; mi < 4; mi++) {
                uint32_t off = (uint32_t)((wm * 64 + mi * 16 + mrow) * ROWB +
                                          (k0u + mcu) * 16);
                ldm_x4(fa_h[mi], ahB + off);
                ldm_x4(fa_l[mi], alB + off);
            }
            uint32_t fb_h[2][4], fb_l[2][4];
#pragma unroll
            for (int hf = 0; hf < 2; hf++) {
                uint32_t off = (uint32_t)((wn * 32 + hf * 16 + mrow) * ROWB +
                                          (k0u + mcu) * 16);
                ldm_x4(fb_h[hf], whB + off);
                ldm_x4(fb_l[hf], wlB + off);
            }
#pragma unroll
            for (int mi = 0; mi < 4; mi++)
#pragma unroll
                for (int nj = 0; nj < 4; nj++) {
                    int hf = nj >> 1;
                    int lo = nj & 1;
                    uint32_t bh[2], bl[2];
                    bh[0] = fb_h[hf][lo];
                    bh[1] = fb_h[hf][lo + 2];
                    bl[0] = fb_l[hf][lo];
                    bl[1] = fb_l[hf][lo + 2];
                    mma_bf16(C[mi][nj], fa_h[mi], bh);
                    mma_bf16(C[mi][nj], fa_h[mi], bl);
                    mma_bf16(C[mi][nj], fa_l[mi], bh);
                }
        }
        __syncthreads();
    }

    // Epilogue
    int g = lane >> 2, t = lane & 3;
#pragma unroll
    for (int mi = 0; mi < 4; mi++) {
#pragma unroll
        for (int nj = 0; nj < 4; nj++) {
            int cbase = col0 + wn * 32 + nj * 8 + t * 2;
#pragma unroll
            for (int rr = 0; rr < 2; rr++) {
                int r = row0 + wm * 64 + mi * 16 + g + rr * 8;
                float vx = C[mi][nj][rr * 2 + 0];
                float vy = C[mi][nj][rr * 2 + 1];
                if (mode == 0) {
                    int b = r >> 11, s = r & 2047, h = cbase >> 6, dd = cbase & 63;
                    if (z < 2) {
                        vx *= g_emb[s * HD + dd];
                        vy *= g_emb[s * HD + dd + 1];
                        if (z == 0) { vx *= 0.125f; vy *= 0.125f; }
                    }
                    __nv_bfloat16 hx = __float2bfloat16(vx);
                    __nv_bfloat16 hy = __float2bfloat16(vy);
                    __nv_bfloat16 lx = __float2bfloat16(vx - __bfloat162float(hx));
                    __nv_bfloat16 ly = __float2bfloat16(vy - __bfloat162float(hy));
                    if (z == 2) {
                        // transposed V: [b,h,d,s]
                        size_t tb = ((size_t)(b * NH + h) * HD + dd) * SEQ + s;
                        g_vth[tb] = hx;        g_vtl[tb] = lx;
                        g_vth[tb + SEQ] = hy;  g_vtl[tb + SEQ] = ly;
                    } else {
                        size_t ib = ((size_t)(b * NH + h) * SEQ + s) * HD + dd;
                        __nv_bfloat16* dh = (z == 0) ? g_qh : g_kh;
                        __nv_bfloat16* dl = (z == 0) ? g_ql : g_kl;
                        *(__nv_bfloat162*)&dh[ib] = __nv_bfloat162(hx, hy);
                        *(__nv_bfloat162*)&dl[ib] = __nv_bfloat162(lx, ly);
                    }
                } else {
                    float2 bv = *(const float2*)&bias[cbase];
                    float2 xv = *(const float2*)&xres[(size_t)r * D_MODEL + cbase];
                    float2 v;
                    v.x = vx + bv.x + xv.x;
                    v.y = vy + bv.y + xv.y;
                    *(float2*)&outp[(size_t)r * D_MODEL + cbase] = v;
                }
            }
        }
    }
}

// ---------------------------------------------------------------------------
// HMMA flash attention: 128 q-rows/CTA, 64-key tiles, 8 warps (16 q-rows each).
// S = (Qh+Ql)(Kh+Kl)^T 3-term; online softmax in fp32 fragments;
// O += (Ph+Pl)(Vh+Vl) 3-term with V pre-transposed in global.
// ---------------------------------------------------------------------------
#define FP 144                            // smem row pitch bytes (64 bf16 + 8 pad)
#define FQH_B 0
#define FQL_B (128 * FP)                  // 18432
#define FKH_B (2 * 128 * FP)              // 36864
#define FKL_B (FKH_B + 64 * FP)
#define FVH_B (FKL_B + 64 * FP)
#define FVL_B (FVH_B + 64 * FP)
#define FMS_B (FVL_B + 64 * FP)           // 73728 (floats)
#define FLASH_SMEM (FMS_B + 64 * 4)       // 73984

__global__ __launch_bounds__(256) void flash_mma_kernel(const unsigned char* __restrict__ kpm) {
    extern __shared__ char fsm[];
    uint32_t s0 = smem_to_u32(fsm);
    float* Ms = (float*)(fsm + FMS_B);

    int tid = threadIdx.x, lane = tid & 31, wid = tid >> 5;
    int qt = blockIdx.x;            // 0..15
    int bh = blockIdx.y;            // 0..63
    int b = bh >> 4, h = bh & 15;
    int q0 = qt * 128;

    int g = lane >> 2, t4 = lane & 3;
    int amat = lane >> 3;
    int mrow = (amat & 1) * 8 + (lane & 7);
    int mcu  = amat >> 1;

    // Load Q tile (hi+lo) via cp.async: 128 rows x 128B each
#pragma unroll
    for (int t = 0; t < 4; t++) {
        int u = tid + t * 256;          // 0..1023
        int r = u >> 3, cu = u & 7;
        size_t gi = ((size_t)bh * SEQ + q0 + r) * HD + cu * 8;
        cp_async16(s0 + FQH_B + r * FP + cu * 16, g_qh + gi);
        cp_async16(s0 + FQL_B + r * FP + cu * 16, g_ql + gi);
    }
    CP_COMMIT();

    float mr[2] = {-INFINITY, -INFINITY};
    float lr[2] = {0.f, 0.f};
    float O[8][4];
#pragma unroll
    for (int j = 0; j < 8; j++)
#pragma unroll
        for (int q = 0; q < 4; q++) O[j][q] = 0.f;

    int rowg = q0 + wid * 16 + g;       // this thread's first q row

    int ktmax = (q0 + 127) >> 6;
    for (int kt = 0; kt <= ktmax; kt++) {
        int k0 = kt * 64;
        // K (hi/lo) rows=keys, V^T (hi/lo) rows=dims — each 64 rows x 128B
#pragma unroll
        for (int t = 0; t < 2; t++) {
            int u = tid + t * 256;      // 0..511
            int r = u >> 3, cu = u & 7;
            size_t ki = ((size_t)bh * SEQ + k0 + r) * HD + cu * 8;
            size_t vi = ((size_t)bh * HD + r) * SEQ + k0 + cu * 8;
            cp_async16(s0 + FKH_B + r * FP + cu * 16, g_kh + ki);
            cp_async16(s0 + FKL_B + r * FP + cu * 16, g_kl + ki);
            cp_async16(s0 + FVH_B + r * FP + cu * 16, g_vth + vi);
            cp_async16(s0 + FVL_B + r * FP + cu * 16, g_vtl + vi);
        }
        if (tid < 64) Ms[tid] = kpm[b * SEQ + k0 + tid] ? -1e30f : 0.f;
        CP_COMMIT(); CP_WAIT0();
        __syncthreads();

        // ---- S = Q K^T (3-term) ----
        float S[8][4];
#pragma unroll
        for (int j = 0; j < 8; j++)
#pragma unroll
            for (int q = 0; q < 4; q++) S[j][q] = 0.f;

#pragma unroll
        for (int ks = 0; ks < 4; ks++) {
            uint32_t qh[4], ql[4];
            uint32_t qoff = (uint32_t)((wid * 16 + mrow) * FP + ks * 32 + mcu * 16);
            ldm_x4(qh, s0 + FQH_B + qoff);
            ldm_x4(ql, s0 + FQL_B + qoff);
            uint32_t kh[4][4], kl[4][4];
#pragma unroll
            for (int grp = 0; grp < 4; grp++) {
                uint32_t koff = (uint32_t)((grp * 16 + mrow) * FP + ks * 32 + mcu * 16);
                ldm_x4(kh[grp], s0 + FKH_B + koff);
                ldm_x4(kl[grp], s0 + FKL_B + koff);
            }
#pragma unroll
            for (int j = 0; j < 8; j++) {
                int grp = j >> 1, lo = j & 1;
                uint32_t bhv[2] = {kh[grp][lo], kh[grp][lo + 2]};
                uint32_t blv[2] = {kl[grp][lo], kl[grp][lo + 2]};
                mma_bf16(S[j], qh, bhv);
                mma_bf16(S[j], qh, blv);
                mma_bf16(S[j], ql, bhv);
            }
        }

        // ---- mask + online softmax (fp32 fragments) ----
        bool needc = (k0 + 63 > q0);
#pragma unroll
        for (int j = 0; j < 8; j++) {
            int c0 = 8 * j + t4 * 2;
            float m0 = Ms[c0], m1 = Ms[c0 + 1];
            float s0v = S[j][0] + m0, s1v = S[j][1] + m1;
            float s2v = S[j][2] + m0, s3v = S[j][3] + m1;
            if (needc) {
                int kc0 = k0 + c0;
                if (kc0 > rowg)          s0v = -1e30f;
                if (kc0 + 1 > rowg)      s1v = -1e30f;
                if (kc0 > rowg + 8)      s2v = -1e30f;
                if (kc0 + 1 > rowg + 8)  s3v = -1e30f;
            }
            S[j][0] = s0v; S[j][1] = s1v; S[j][2] = s2v; S[j][3] = s3v;
        }
        float mt0 = -1e30f, mt1 = -1e30f;
#pragma unroll
        for (int j = 0; j < 8; j++) {
            mt0 = fmaxf(mt0, fmaxf(S[j][0], S[j][1]));
            mt1 = fmaxf(mt1, fmaxf(S[j][2], S[j][3]));
        }
        mt0 = fmaxf(mt0, __shfl_xor_sync(0xffffffffu, mt0, 1));
        mt0 = fmaxf(mt0, __shfl_xor_sync(0xffffffffu, mt0, 2));
        mt1 = fmaxf(mt1, __shfl_xor_sync(0xffffffffu, mt1, 1));
        mt1 = fmaxf(mt1, __shfl_xor_sync(0xffffffffu, mt1, 2));
        float mn0 = fmaxf(mr[0], mt0), mn1 = fmaxf(mr[1], mt1);
        float corr0 = __expf(mr[0] - mn0), corr1 = __expf(mr[1] - mn1);
        mr[0] = mn0; mr[1] = mn1;
        float rs0 = 0.f, rs1 = 0.f;
#pragma unroll
        for (int j = 0; j < 8; j++) {
            S[j][0] = __expf(S[j][0] - mn0);
            S[j][1] = __expf(S[j][1] - mn0);
            S[j][2] = __expf(S[j][2] - mn1);
            S[j][3] = __expf(S[j][3] - mn1);
            rs0 += S[j][0] + S[j][1];
            rs1 += S[j][2] + S[j][3];
        }
        rs0 += __shfl_xor_sync(0xffffffffu, rs0, 1);
        rs0 += __shfl_xor_sync(0xffffffffu, rs0, 2);
        rs1 += __shfl_xor_sync(0xffffffffu, rs1, 1);
        rs1 += __shfl_xor_sync(0xffffffffu, rs1, 2);
        lr[0] = lr[0] * corr0 + rs0;
        lr[1] = lr[1] * corr1 + rs1;
#pragma unroll
        for (int j = 0; j < 8; j++) {
            O[j][0] *= corr0; O[j][1] *= corr0;
            O[j][2] *= corr1; O[j][3] *= corr1;
        }

        // ---- O += P V (3-term); P fragments from S, V^T as B operand ----
#pragma unroll
        for (int ks = 0; ks < 4; ks++) {
            int j0 = 2 * ks, j1 = 2 * ks + 1;
            uint32_t pah[4], pal[4];
            {
                float a0 = S[j0][0], a1 = S[j0][1], a2 = S[j0][2], a3 = S[j0][3];
                float b0 = S[j1][0], b1 = S[j1][1], b2 = S[j1][2], b3 = S[j1][3];
                pah[0] = pack_bf16x2(a0, a1);
                pah[1] = pack_bf16x2(a2, a3);
                pah[2] = pack_bf16x2(b0, b1);
                pah[3] = pack_bf16x2(b2, b3);
                pal[0] = pack_bf16x2(a0 - __bfloat162float(__float2bfloat16(a0)),
                                     a1 - __bfloat162float(__float2bfloat16(a1)));
                pal[1] = pack_bf16x2(a2 - __bfloat162float(__float2bfloat16(a2)),
                                     a3 - __bfloat162float(__float2bfloat16(a3)));
                pal[2] = pack_bf16x2(b0 - __bfloat162float(__float2bfloat16(b0)),
                                     b1 - __bfloat162float(__float2bfloat16(b1)));
                pal[3] = pack_bf16x2(b2 - __bfloat162float(__float2bfloat16(b2)),
                                     b3 - __bfloat162float(__float2bfloat16(b3)));
            }
            uint32_t vh[4][4], vl[4][4];
#pragma unroll
            for (int grp = 0; grp < 4; grp++) {
                uint32_t voff = (uint32_t)((grp * 16 + mrow) * FP + ks * 32 + mcu * 16);
                ldm_x4(vh[grp], s0 + FVH_B + voff);
                ldm_x4(vl[grp], s0 + FVL_B + voff);
            }
#pragma unroll
            for (int jd = 0; jd < 8; jd++) {
                int grp = jd >> 1, lo = jd & 1;
                uint32_t bhv[2] = {vh[grp][lo], vh[grp][lo + 2]};
                uint32_t blv[2] = {vl[grp][lo], vl[grp][lo + 2]};
                mma_bf16(O[jd], pah, bhv);
                mma_bf16(O[jd], pah, blv);
                mma_bf16(O[jd], pal, bhv);
            }
        }
        __syncthreads();
    }

    // ---- epilogue: normalize, write bf16 hi/lo to [B,S,D] for out-proj ----
    float inv0 = 1.f / lr[0], inv1 = 1.f / lr[1];
#pragma unroll
    for (int j = 0; j < 8; j++) {
        int dd = h * HD + 8 * j + t4 * 2;
        {
            float vx = O[j][0] * inv0, vy = O[j][1] * inv0;
            size_t idx = (size_t)(b * SEQ + rowg) * D_MODEL + dd;
            __nv_bfloat16 hx = __float2bfloat16(vx), hy = __float2bfloat16(vy);
            *(__nv_bfloat162*)&g_ah[idx] = __nv_bfloat162(hx, hy);
            *(__nv_bfloat162*)&g_al[idx] =
                __nv_bfloat162(__float2bfloat16(vx - __bfloat162float(hx)),
                               __float2bfloat16(vy - __bfloat162float(hy)));
        }
        {
            float vx = O[j][2] * inv1, vy = O[j][3] * inv1;
            size_t idx = (size_t)(b * SEQ + rowg + 8) * D_MODEL + dd;
            __nv_bfloat16 hx = __float2bfloat16(vx), hy = __float2bfloat16(vy);
            *(__nv_bfloat162*)&g_ah[idx] = __nv_bfloat162(hx, hy);
            *(__nv_bfloat162*)&g_al[idx] =
                __nv_bfloat162(__float2bfloat16(vx - __bfloat162float(hx)),
                               __float2bfloat16(vy - __bfloat162float(hy)));
        }
    }
}

// ---------------------------------------------------------------------------
extern "C" void kernel_launch(void* const* d_in, const int* in_sizes, int n_in,
                              void* d_out, int out_size) {
    const float* x            = (const float*)d_in[0];
    const unsigned char* kpm  = (const unsigned char*)d_in[1];
    const float* q_w          = (const float*)d_in[2];
    const float* k_w          = (const float*)d_in[3];
    const float* v_w          = (const float*)d_in[4];
    const float* out_w        = (const float*)d_in[5];
    const float* out_b        = (const float*)d_in[6];
    const float* ln_g         = (const float*)d_in[7];
    const float* ln_b         = (const float*)d_in[8];
    float* out = (float*)d_out;

    cudaFuncSetAttribute(flash_mma_kernel, cudaFuncAttributeMaxDynamicSharedMemorySize, FLASH_SMEM);
    cudaFuncSetAttribute(mma_gemm_kernel, cudaFuncAttributeMaxDynamicSharedMemorySize, GEMM_SMEM);

    emb_kernel<<<SEQ, HD>>>();
    wconv_kernel<<<(4 * D_MODEL * D_MODEL) / 256, 256>>>(q_w, k_w, v_w, out_w);
    ln_kernel<<<ROWS, 256>>>(x, ln_g, ln_b);
    mma_gemm_kernel<<<dim3(D_MODEL / BN, ROWS / BM, 3), 256, GEMM_SMEM>>>(
        0, nullptr, nullptr, nullptr);
    flash_mma_kernel<<<dim3(16, 64), 256, FLASH_SMEM>>>(kpm);
    mma_gemm_kernel<<<dim3(D_MODEL / BN, ROWS / BM, 1), 256, GEMM_SMEM>>>(
        1, out_b, x, out);
}

// round 12
// speedup vs baseline: 2.3109x; 1.0319x over previous
#include <cuda_runtime.h>
#include <cuda_bf16.h>
#include <math.h>
#include <cstdint>

#define D_MODEL 1024
#define SEQ     2048
#define BATCH   4
#define NH      16
#define HD      64
#define ROWS    (BATCH * SEQ)   // 8192

// ---------------------------------------------------------------------------
// Device-global scratch (no runtime allocation allowed)
// ---------------------------------------------------------------------------
__device__ float g_emb[SEQ * HD];
__device__ __nv_bfloat16 g_qh[ROWS * D_MODEL];   // Q (rot, pre-scaled) hi  [b,h,s,d]
__device__ __nv_bfloat16 g_ql[ROWS * D_MODEL];   // lo
__device__ __nv_bfloat16 g_kh[ROWS * D_MODEL];   // K (rot) hi             [b,h,s,d]
__device__ __nv_bfloat16 g_kl[ROWS * D_MODEL];   // lo
__device__ __nv_bfloat16 g_vth[ROWS * D_MODEL];  // V hi TRANSPOSED        [b,h,d,s]
__device__ __nv_bfloat16 g_vtl[ROWS * D_MODEL];  // lo
__device__ __nv_bfloat16 g_xh[ROWS * D_MODEL];   // ln(x) hi
__device__ __nv_bfloat16 g_xl[ROWS * D_MODEL];   // ln(x) lo
__device__ __nv_bfloat16 g_ah[ROWS * D_MODEL];   // attention out hi
__device__ __nv_bfloat16 g_al[ROWS * D_MODEL];   // attention out lo
__device__ __nv_bfloat16 g_wh[4 * D_MODEL * D_MODEL];  // q,k,v,out weights hi
__device__ __nv_bfloat16 g_wl[4 * D_MODEL * D_MODEL];  // lo

// ---------------------------------------------------------------------------
// PTX helpers: ldmatrix / mma.sync bf16 / cp.async (all baseline sm_80+ ISA)
// ---------------------------------------------------------------------------
__device__ __forceinline__ uint32_t smem_to_u32(const void* smem_ptr) {
    uint32_t addr;
    asm("{ .reg .u64 tmp; cvta.to.shared.u64 tmp, %1; cvt.u32.u64 %0, tmp; }"
        : "=r"(addr) : "l"(smem_ptr));
    return addr;
}
__device__ __forceinline__ void ldm_x4(uint32_t* r, uint32_t addr) {
    asm volatile("ldmatrix.sync.aligned.m8n8.x4.shared.b16 {%0,%1,%2,%3}, [%4];"
        : "=r"(r[0]), "=r"(r[1]), "=r"(r[2]), "=r"(r[3]) : "r"(addr));
}
__device__ __forceinline__ void mma_bf16(float* c, const uint32_t* a, const uint32_t* b) {
    asm volatile(
        "mma.sync.aligned.m16n8k16.row.col.f32.bf16.bf16.f32 "
        "{%0,%1,%2,%3}, {%4,%5,%6,%7}, {%8,%9}, {%0,%1,%2,%3};"
        : "+f"(c[0]), "+f"(c[1]), "+f"(c[2]), "+f"(c[3])
        : "r"(a[0]), "r"(a[1]), "r"(a[2]), "r"(a[3]), "r"(b[0]), "r"(b[1]));
}
__device__ __forceinline__ void cp_async16(uint32_t smem, const void* gptr) {
    asm volatile("cp.async.cg.shared.global [%0], [%1], 16;"
        :: "r"(smem), "l"(gptr));
}
#define CP_COMMIT() asm volatile("cp.async.commit_group;" ::: "memory")
#define CP_WAIT1()  asm volatile("cp.async.wait_group 1;" ::: "memory")
#define CP_WAIT0()  asm volatile("cp.async.wait_group 0;" ::: "memory")

__device__ __forceinline__ uint32_t pack_bf16x2(float lo, float hi) {
    __nv_bfloat162 p(__float2bfloat16(lo), __float2bfloat16(hi));
    return *(uint32_t*)&p;
}

// ---------------------------------------------------------------------------
// Rotary emb table (double precision — args reach ~2048 rad)
// ---------------------------------------------------------------------------
__global__ __launch_bounds__(256) void emb_kernel() {
    int idx = blockIdx.x * 256 + threadIdx.x;   // 0 .. SEQ*HD-1
    int s = idx >> 6;
    int d = idx & 63;
    int i = d & 31;
    double f = exp(-log(10000.0) * (double)i / 32.0);
    double a = (double)s * f;
    g_emb[idx] = (d < 32) ? (float)sin(a) : (float)cos(a);
}

// ---------------------------------------------------------------------------
// Weight hi/lo bf16 split: 4 x 1024x1024
// ---------------------------------------------------------------------------
__global__ __launch_bounds__(256) void wconv_kernel(const float* __restrict__ q,
                                                    const float* __restrict__ k,
                                                    const float* __restrict__ v,
                                                    const float* __restrict__ o) {
    int i = blockIdx.x * 256 + threadIdx.x;   // 0 .. 4M-1
    int m = i >> 20;
    const float* src = (m == 0) ? q : (m == 1) ? k : (m == 2) ? v : o;
    float val = src[i & 0xFFFFF];
    __nv_bfloat16 h = __float2bfloat16(val);
    g_wh[i] = h;
    g_wl[i] = __float2bfloat16(val - __bfloat162float(h));
}

// ---------------------------------------------------------------------------
// LayerNorm fused with bf16 hi/lo split output
// ---------------------------------------------------------------------------
__global__ __launch_bounds__(256) void ln_kernel(const float* __restrict__ x,
                                                 const float* __restrict__ g,
                                                 const float* __restrict__ b) {
    int row = blockIdx.x;
    int tid = threadIdx.x;
    const float* xr = x + (size_t)row * D_MODEL;
    float4 v = *(const float4*)(xr + tid * 4);
    float s1 = v.x + v.y + v.z + v.w;
    float s2 = v.x * v.x + v.y * v.y + v.z * v.z + v.w * v.w;
#pragma unroll
    for (int off = 16; off; off >>= 1) {
        s1 += __shfl_xor_sync(0xffffffffu, s1, off);
        s2 += __shfl_xor_sync(0xffffffffu, s2, off);
    }
    __shared__ float r1[8], r2[8];
    int w = tid >> 5, lane = tid & 31;
    if (lane == 0) { r1[w] = s1; r2[w] = s2; }
    __syncthreads();
    float t1 = 0.f, t2 = 0.f;
#pragma unroll
    for (int i = 0; i < 8; i++) { t1 += r1[i]; t2 += r2[i]; }
    float mu   = t1 * (1.f / D_MODEL);
    float var  = t2 * (1.f / D_MODEL) - mu * mu;
    float rstd = rsqrtf(var + 1e-5f);
    float4 gv = *(const float4*)(g + tid * 4);
    float4 bv = *(const float4*)(b + tid * 4);
    float o0 = (v.x - mu) * rstd * gv.x + bv.x;
    float o1 = (v.y - mu) * rstd * gv.y + bv.y;
    float o2 = (v.z - mu) * rstd * gv.z + bv.z;
    float o3 = (v.w - mu) * rstd * gv.w + bv.w;
    size_t base = (size_t)row * D_MODEL + tid * 4;
    __nv_bfloat16 h0 = __float2bfloat16(o0), h1 = __float2bfloat16(o1);
    __nv_bfloat16 h2 = __float2bfloat16(o2), h3 = __float2bfloat16(o3);
    *(__nv_bfloat162*)&g_xh[base]     = __nv_bfloat162(h0, h1);
    *(__nv_bfloat162*)&g_xh[base + 2] = __nv_bfloat162(h2, h3);
    *(__nv_bfloat162*)&g_xl[base] =
        __nv_bfloat162(__float2bfloat16(o0 - __bfloat162float(h0)),
                       __float2bfloat16(o1 - __bfloat162float(h1)));
    *(__nv_bfloat162*)&g_xl[base + 2] =
        __nv_bfloat162(__float2bfloat16(o2 - __bfloat162float(h2)),
                       __float2bfloat16(o3 - __bfloat162float(h3)));
}

// ---------------------------------------------------------------------------
// HMMA bf16-split GEMM:  C[128x128 tile] = A[M,1024] @ W[N,1024]^T
// 3-term mma issued in three independent passes (no back-to-back RAW on the
// same C fragment). mode 0: QKV (+rot, q scaled, v transposed); mode 1: out-proj.
// ---------------------------------------------------------------------------
#define BM 128
#define BN 128
#define BK 32
#define ROWB 80                          // padded smem row bytes (32 bf16 + pad)
#define MAT_BYTES (128 * ROWB)           // 10240
#define BUF_BYTES (4 * MAT_BYTES)        // Ah, Al, Wh, Wl
#define GEMM_SMEM (2 * BUF_BYTES)        // 81920

__global__ __launch_bounds__(256) void mma_gemm_kernel(int mode,
                                                       const float* __restrict__ bias,
                                                       const float* __restrict__ xres,
                                                       float* __restrict__ outp) {
    extern __shared__ char dsm[];
    uint32_t s0 = smem_to_u32(dsm);
    int tid = threadIdx.x, lane = tid & 31, wid = tid >> 5;
    int wm = wid >> 2, wn = wid & 3;
    int z = blockIdx.z;
    int row0 = blockIdx.y * BM;
    int col0 = blockIdx.x * BN;

    const __nv_bfloat16* Ah = (mode == 0) ? g_xh : g_ah;
    const __nv_bfloat16* Al = (mode == 0) ? g_xl : g_al;
    int widx = (mode == 0) ? z : 3;
    const __nv_bfloat16* Wh = g_wh + (size_t)widx * D_MODEL * D_MODEL;
    const __nv_bfloat16* Wl = g_wl + (size_t)widx * D_MODEL * D_MODEL;

    const __nv_bfloat16* srcs[4] = {Ah, Al, Wh, Wl};
    int rbase[4] = {row0, row0, col0, col0};

    float C[4][4][4];
#pragma unroll
    for (int mi = 0; mi < 4; mi++)
#pragma unroll
        for (int nj = 0; nj < 4; nj++)
#pragma unroll
            for (int q = 0; q < 4; q++) C[mi][nj][q] = 0.f;

    auto load_chunk = [&](int c, int bi) {
        int kt = c * BK;
        uint32_t sb = s0 + bi * BUF_BYTES;
#pragma unroll
        for (int m = 0; m < 4; m++) {
            const __nv_bfloat16* src = srcs[m];
            int rb = rbase[m];
#pragma unroll
            for (int rep = 0; rep < 2; rep++) {
                int u = tid + rep * 256;      // 0..511
                int r = u >> 2, cu = u & 3;
                cp_async16(sb + m * MAT_BYTES + r * ROWB + cu * 16,
                           src + (size_t)(rb + r) * D_MODEL + kt + cu * 8);
            }
        }
    };

    int amat = lane >> 3;                       // 0..3
    int mrow = (amat & 1) * 8 + (lane & 7);     // row offset within 16-row tile
    int mcu  = amat >> 1;                       // k-unit (16B) offset

    load_chunk(0, 0);
    CP_COMMIT();

    for (int c = 0; c < 32; c++) {
        int bi = c & 1;
        if (c < 32 - 1) { load_chunk(c + 1, bi ^ 1); CP_COMMIT(); CP_WAIT1(); }
        else            { CP_WAIT0(); }
        __syncthreads();

        uint32_t ahB = s0 + bi * BUF_BYTES;
        uint32_t alB = ahB + MAT_BYTES;
        uint32_t whB = ahB + 2 * MAT_BYTES;
        uint32_t wlB = ahB + 3 * MAT_BYTES;

#pragma unroll
        for (int ks = 0; ks < 2; ks++) {
            int k0u = ks * 2;
            uint32_t fa_h[4][4], fa_l[4][4];
#pragma unroll
            for (int mi = 0; mi < 4; mi++) {
                uint32_t off = (uint32_t)((wm * 64 + mi * 16 + mrow) * ROWB +
                                          (k0u + mcu) * 16);
                ldm_x4(fa_h[mi], ahB + off);
                ldm_x4(fa_l[mi], alB + off);
            }
            uint32_t fb_h[2][4], fb_l[2][4];
#pragma unroll
            for (int hf = 0; hf < 2; hf++) {
                uint32_t off = (uint32_t)((wn * 32 + hf * 16 + mrow) * ROWB +
                                          (k0u + mcu) * 16);
                ldm_x4(fb_h[hf], whB + off);
                ldm_x4(fb_l[hf], wlB + off);
            }
            // Pass 1: Ah * Wh  (16 independent accumulators back-to-back)
#pragma unroll
            for (int mi = 0; mi < 4; mi++)
#pragma unroll
                for (int nj = 0; nj < 4; nj++) {
                    int hf = nj >> 1, lo = nj & 1;
                    uint32_t bv[2] = {fb_h[hf][lo], fb_h[hf][lo + 2]};
                    mma_bf16(C[mi][nj], fa_h[mi], bv);
                }
            // Pass 2: Ah * Wl
#pragma unroll
            for (int mi = 0; mi < 4; mi++)
#pragma unroll
                for (int nj = 0; nj < 4; nj++) {
                    int hf = nj >> 1, lo = nj & 1;
                    uint32_t bv[2] = {fb_l[hf][lo], fb_l[hf][lo + 2]};
                    mma_bf16(C[mi][nj], fa_h[mi], bv);
                }
            // Pass 3: Al * Wh
#pragma unroll
            for (int mi = 0; mi < 4; mi++)
#pragma unroll
                for (int nj = 0; nj < 4; nj++) {
                    int hf = nj >> 1, lo = nj & 1;
                    uint32_t bv[2] = {fb_h[hf][lo], fb_h[hf][lo + 2]};
                    mma_bf16(C[mi][nj], fa_l[mi], bv);
                }
        }
        __syncthreads();
    }

    // Epilogue
    int g = lane >> 2, t = lane & 3;
#pragma unroll
    for (int mi = 0; mi < 4; mi++) {
#pragma unroll
        for (int nj = 0; nj < 4; nj++) {
            int cbase = col0 + wn * 32 + nj * 8 + t * 2;
#pragma unroll
            for (int rr = 0; rr < 2; rr++) {
                int r = row0 + wm * 64 + mi * 16 + g + rr * 8;
                float vx = C[mi][nj][rr * 2 + 0];
                float vy = C[mi][nj][rr * 2 + 1];
                if (mode == 0) {
                    int b = r >> 11, s = r & 2047, h = cbase >> 6, dd = cbase & 63;
                    if (z < 2) {
                        vx *= g_emb[s * HD + dd];
                        vy *= g_emb[s * HD + dd + 1];
                        if (z == 0) { vx *= 0.125f; vy *= 0.125f; }
                    }
                    __nv_bfloat16 hx = __float2bfloat16(vx);
                    __nv_bfloat16 hy = __float2bfloat16(vy);
                    __nv_bfloat16 lx = __float2bfloat16(vx - __bfloat162float(hx));
                    __nv_bfloat16 ly = __float2bfloat16(vy - __bfloat162float(hy));
                    if (z == 2) {
                        // transposed V: [b,h,d,s]
                        size_t tb = ((size_t)(b * NH + h) * HD + dd) * SEQ + s;
                        g_vth[tb] = hx;        g_vtl[tb] = lx;
                        g_vth[tb + SEQ] = hy;  g_vtl[tb + SEQ] = ly;
                    } else {
                        size_t ib = ((size_t)(b * NH + h) * SEQ + s) * HD + dd;
                        __nv_bfloat16* dh = (z == 0) ? g_qh : g_kh;
                        __nv_bfloat16* dl = (z == 0) ? g_ql : g_kl;
                        *(__nv_bfloat162*)&dh[ib] = __nv_bfloat162(hx, hy);
                        *(__nv_bfloat162*)&dl[ib] = __nv_bfloat162(lx, ly);
                    }
                } else {
                    float2 bv = *(const float2*)&bias[cbase];
                    float2 xv = *(const float2*)&xres[(size_t)r * D_MODEL + cbase];
                    float2 v;
                    v.x = vx + bv.x + xv.x;
                    v.y = vy + bv.y + xv.y;
                    *(float2*)&outp[(size_t)r * D_MODEL + cbase] = v;
                }
            }
        }
    }
}

// ---------------------------------------------------------------------------
// HMMA flash attention: 128 q-rows/CTA, 64-key tiles, 8 warps (16 q-rows each).
// Double-buffered K/V/mask smem stages; one __syncthreads per kt iteration:
//   wait(all cp.async) -> sync -> prefetch kt+1 -> compute kt
// Heavy-first CTA order (qt reversed) to shrink the causal tail wave.
// ---------------------------------------------------------------------------
#define FP 144                            // smem row pitch bytes (64 bf16 + 8 pad)
#define FQH_B 0
#define FQL_B (128 * FP)                  // 18432
#define KV0_B (2 * 128 * FP)              // 36864
#define KVSTAGE_B (4 * 64 * FP)           // 36864
#define KH_OFF 0
#define KL_OFF (64 * FP)
#define VH_OFF (2 * 64 * FP)
#define VL_OFF (3 * 64 * FP)
#define FMS_B (KV0_B + 2 * KVSTAGE_B)     // 110592
#define FLASH_SMEM (FMS_B + 2 * 64 * 4)   // 111104

__global__ __launch_bounds__(256) void flash_mma_kernel(const unsigned char* __restrict__ kpm) {
    extern __shared__ char fsm[];
    uint32_t s0 = smem_to_u32(fsm);
    float* Ms = (float*)(fsm + FMS_B);

    int tid = threadIdx.x, lane = tid & 31, wid = tid >> 5;
    int qt = (int)gridDim.x - 1 - (int)blockIdx.x;   // heavy tiles first
    int bh = blockIdx.y;            // 0..63
    int b = bh >> 4, h = bh & 15;
    int q0 = qt * 128;

    int g = lane >> 2, t4 = lane & 3;
    int amat = lane >> 3;
    int mrow = (amat & 1) * 8 + (lane & 7);
    int mcu  = amat >> 1;

    auto load_kv = [&](int kt, int stage) {
        int k0 = kt * 64;
        uint32_t kb = s0 + KV0_B + stage * KVSTAGE_B;
#pragma unroll
        for (int t = 0; t < 2; t++) {
            int u = tid + t * 256;      // 0..511
            int r = u >> 3, cu = u & 7;
            size_t ki = ((size_t)bh * SEQ + k0 + r) * HD + cu * 8;
            size_t vi = ((size_t)bh * HD + r) * SEQ + k0 + cu * 8;
            cp_async16(kb + KH_OFF + r * FP + cu * 16, g_kh + ki);
            cp_async16(kb + KL_OFF + r * FP + cu * 16, g_kl + ki);
            cp_async16(kb + VH_OFF + r * FP + cu * 16, g_vth + vi);
            cp_async16(kb + VL_OFF + r * FP + cu * 16, g_vtl + vi);
        }
    };

    // Initial: Q tile (hi+lo) + KV stage 0 + mask slot 0
#pragma unroll
    for (int t = 0; t < 4; t++) {
        int u = tid + t * 256;          // 0..1023
        int r = u >> 3, cu = u & 7;
        size_t gi = ((size_t)bh * SEQ + q0 + r) * HD + cu * 8;
        cp_async16(s0 + FQH_B + r * FP + cu * 16, g_qh + gi);
        cp_async16(s0 + FQL_B + r * FP + cu * 16, g_ql + gi);
    }
    load_kv(0, 0);
    if (tid < 64) Ms[tid] = kpm[b * SEQ + tid] ? -1e30f : 0.f;
    CP_COMMIT();

    float mr[2] = {-INFINITY, -INFINITY};
    float lr[2] = {0.f, 0.f};
    float O[8][4];
#pragma unroll
    for (int j = 0; j < 8; j++)
#pragma unroll
        for (int q = 0; q < 4; q++) O[j][q] = 0.f;

    int rowg = q0 + wid * 16 + g;       // this thread's first q row

    int ktmax = (q0 + 127) >> 6;
    for (int kt = 0; kt <= ktmax; kt++) {
        int bi = kt & 1;
        int k0 = kt * 64;
        CP_WAIT0();
        __syncthreads();
        if (kt < ktmax) {
            load_kv(kt + 1, bi ^ 1);
            CP_COMMIT();
            if (tid < 64)
                Ms[(bi ^ 1) * 64 + tid] =
                    kpm[b * SEQ + (kt + 1) * 64 + tid] ? -1e30f : 0.f;
        }
        uint32_t kvb = s0 + KV0_B + bi * KVSTAGE_B;
        float* Msl = Ms + bi * 64;

        // ---- S = Q K^T (3-term, pass-separated) ----
        float S[8][4];
#pragma unroll
        for (int j = 0; j < 8; j++)
#pragma unroll
            for (int q = 0; q < 4; q++) S[j][q] = 0.f;

#pragma unroll
        for (int ks = 0; ks < 4; ks++) {
            uint32_t qh[4], ql[4];
            uint32_t qoff = (uint32_t)((wid * 16 + mrow) * FP + ks * 32 + mcu * 16);
            ldm_x4(qh, s0 + FQH_B + qoff);
            ldm_x4(ql, s0 + FQL_B + qoff);
            uint32_t kh[4][4], kl[4][4];
#pragma unroll
            for (int grp = 0; grp < 4; grp++) {
                uint32_t koff = (uint32_t)((grp * 16 + mrow) * FP + ks * 32 + mcu * 16);
                ldm_x4(kh[grp], kvb + KH_OFF + koff);
                ldm_x4(kl[grp], kvb + KL_OFF + koff);
            }
#pragma unroll
            for (int j = 0; j < 8; j++) {
                int grp = j >> 1, lo = j & 1;
                uint32_t bv[2] = {kh[grp][lo], kh[grp][lo + 2]};
                mma_bf16(S[j], qh, bv);
            }
#pragma unroll
            for (int j = 0; j < 8; j++) {
                int grp = j >> 1, lo = j & 1;
                uint32_t bv[2] = {kl[grp][lo], kl[grp][lo + 2]};
                mma_bf16(S[j], qh, bv);
            }
#pragma unroll
            for (int j = 0; j < 8; j++) {
                int grp = j >> 1, lo = j & 1;
                uint32_t bv[2] = {kh[grp][lo], kh[grp][lo + 2]};
                mma_bf16(S[j], ql, bv);
            }
        }

        // ---- mask + online softmax (fp32 fragments) ----
        bool needc = (k0 + 63 > q0);
#pragma unroll
        for (int j = 0; j < 8; j++) {
            int c0 = 8 * j + t4 * 2;
            float m0 = Msl[c0], m1 = Msl[c0 + 1];
            float s0v = S[j][0] + m0, s1v = S[j][1] + m1;
            float s2v = S[j][2] + m0, s3v = S[j][3] + m1;
            if (needc) {
                int kc0 = k0 + c0;
                if (kc0 > rowg)          s0v = -1e30f;
                if (kc0 + 1 > rowg)      s1v = -1e30f;
                if (kc0 > rowg + 8)      s2v = -1e30f;
                if (kc0 + 1 > rowg + 8)  s3v = -1e30f;
            }
            S[j][0] = s0v; S[j][1] = s1v; S[j][2] = s2v; S[j][3] = s3v;
        }
        float mt0 = -1e30f, mt1 = -1e30f;
#pragma unroll
        for (int j = 0; j < 8; j++) {
            mt0 = fmaxf(mt0, fmaxf(S[j][0], S[j][1]));
            mt1 = fmaxf(mt1, fmaxf(S[j][2], S[j][3]));
        }
        mt0 = fmaxf(mt0, __shfl_xor_sync(0xffffffffu, mt0, 1));
        mt0 = fmaxf(mt0, __shfl_xor_sync(0xffffffffu, mt0, 2));
        mt1 = fmaxf(mt1, __shfl_xor_sync(0xffffffffu, mt1, 1));
        mt1 = fmaxf(mt1, __shfl_xor_sync(0xffffffffu, mt1, 2));
        float mn0 = fmaxf(mr[0], mt0), mn1 = fmaxf(mr[1], mt1);
        float corr0 = __expf(mr[0] - mn0), corr1 = __expf(mr[1] - mn1);
        mr[0] = mn0; mr[1] = mn1;
        float rs0 = 0.f, rs1 = 0.f;
#pragma unroll
        for (int j = 0; j < 8; j++) {
            S[j][0] = __expf(S[j][0] - mn0);
            S[j][1] = __expf(S[j][1] - mn0);
            S[j][2] = __expf(S[j][2] - mn1);
            S[j][3] = __expf(S[j][3] - mn1);
            rs0 += S[j][0] + S[j][1];
            rs1 += S[j][2] + S[j][3];
        }
        rs0 += __shfl_xor_sync(0xffffffffu, rs0, 1);
        rs0 += __shfl_xor_sync(0xffffffffu, rs0, 2);
        rs1 += __shfl_xor_sync(0xffffffffu, rs1, 1);
        rs1 += __shfl_xor_sync(0xffffffffu, rs1, 2);
        lr[0] = lr[0] * corr0 + rs0;
        lr[1] = lr[1] * corr1 + rs1;
#pragma unroll
        for (int j = 0; j < 8; j++) {
            O[j][0] *= corr0; O[j][1] *= corr0;
            O[j][2] *= corr1; O[j][3] *= corr1;
        }

        // ---- O += P V (3-term, pass-separated); V^T as B operand ----
#pragma unroll
        for (int ks = 0; ks < 4; ks++) {
            int j0 = 2 * ks, j1 = 2 * ks + 1;
            uint32_t pah[4], pal[4];
            {
                float a0 = S[j0][0], a1 = S[j0][1], a2 = S[j0][2], a3 = S[j0][3];
                float b0 = S[j1][0], b1 = S[j1][1], b2 = S[j1][2], b3 = S[j1][3];
                pah[0] = pack_bf16x2(a0, a1);
                pah[1] = pack_bf16x2(a2, a3);
                pah[2] = pack_bf16x2(b0, b1);
                pah[3] = pack_bf16x2(b2, b3);
                pal[0] = pack_bf16x2(a0 - __bfloat162float(__float2bfloat16(a0)),
                                     a1 - __bfloat162float(__float2bfloat16(a1)));
                pal[1] = pack_bf16x2(a2 - __bfloat162float(__float2bfloat16(a2)),
                                     a3 - __bfloat162float(__float2bfloat16(a3)));
                pal[2] = pack_bf16x2(b0 - __bfloat162float(__float2bfloat16(b0)),
                                     b1 - __bfloat162float(__float2bfloat16(b1)));
                pal[3] = pack_bf16x2(b2 - __bfloat162float(__float2bfloat16(b2)),
                                     b3 - __bfloat162float(__float2bfloat16(b3)));
            }
            uint32_t vh[4][4], vl[4][4];
#pragma unroll
            for (int grp = 0; grp < 4; grp++) {
                uint32_t voff = (uint32_t)((grp * 16 + mrow) * FP + ks * 32 + mcu * 16);
                ldm_x4(vh[grp], kvb + VH_OFF + voff);
                ldm_x4(vl[grp], kvb + VL_OFF + voff);
            }
#pragma unroll
            for (int jd = 0; jd < 8; jd++) {
                int grp = jd >> 1, lo = jd & 1;
                uint32_t bv[2] = {vh[grp][lo], vh[grp][lo + 2]};
                mma_bf16(O[jd], pah, bv);
            }
#pragma unroll
            for (int jd = 0; jd < 8; jd++) {
                int grp = jd >> 1, lo = jd & 1;
                uint32_t bv[2] = {vl[grp][lo], vl[grp][lo + 2]};
                mma_bf16(O[jd], pah, bv);
            }
#pragma unroll
            for (int jd = 0; jd < 8; jd++) {
                int grp = jd >> 1, lo = jd & 1;
                uint32_t bv[2] = {vh[grp][lo], vh[grp][lo + 2]};
                mma_bf16(O[jd], pal, bv);
            }
        }
    }

    // ---- epilogue: normalize, write bf16 hi/lo to [B,S,D] for out-proj ----
    float inv0 = 1.f / lr[0], inv1 = 1.f / lr[1];
#pragma unroll
    for (int j = 0; j < 8; j++) {
        int dd = h * HD + 8 * j + t4 * 2;
        {
            float vx = O[j][0] * inv0, vy = O[j][1] * inv0;
            size_t idx = (size_t)(b * SEQ + rowg) * D_MODEL + dd;
            __nv_bfloat16 hx = __float2bfloat16(vx), hy = __float2bfloat16(vy);
            *(__nv_bfloat162*)&g_ah[idx] = __nv_bfloat162(hx, hy);
            *(__nv_bfloat162*)&g_al[idx] =
                __nv_bfloat162(__float2bfloat16(vx - __bfloat162float(hx)),
                               __float2bfloat16(vy - __bfloat162float(hy)));
        }
        {
            float vx = O[j][2] * inv1, vy = O[j][3] * inv1;
            size_t idx = (size_t)(b * SEQ + rowg + 8) * D_MODEL + dd;
            __nv_bfloat16 hx = __float2bfloat16(vx), hy = __float2bfloat16(vy);
            *(__nv_bfloat162*)&g_ah[idx] = __nv_bfloat162(hx, hy);
            *(__nv_bfloat162*)&g_al[idx] =
                __nv_bfloat162(__float2bfloat16(vx - __bfloat162float(hx)),
                               __float2bfloat16(vy - __bfloat162float(hy)));
        }
    }
}

// ---------------------------------------------------------------------------
extern "C" void kernel_launch(void* const* d_in, const int* in_sizes, int n_in,
                              void* d_out, int out_size) {
    const float* x            = (const float*)d_in[0];
    const unsigned char* kpm  = (const unsigned char*)d_in[1];
    const float* q_w          = (const float*)d_in[2];
    const float* k_w          = (const float*)d_in[3];
    const float* v_w          = (const float*)d_in[4];
    const float* out_w        = (const float*)d_in[5];
    const float* out_b        = (const float*)d_in[6];
    const float* ln_g         = (const float*)d_in[7];
    const float* ln_b         = (const float*)d_in[8];
    float* out = (float*)d_out;

    cudaFuncSetAttribute(flash_mma_kernel, cudaFuncAttributeMaxDynamicSharedMemorySize, FLASH_SMEM);
    cudaFuncSetAttribute(mma_gemm_kernel, cudaFuncAttributeMaxDynamicSharedMemorySize, GEMM_SMEM);

    emb_kernel<<<(SEQ * HD) / 256, 256>>>();
    wconv_kernel<<<(4 * D_MODEL * D_MODEL) / 256, 256>>>(q_w, k_w, v_w, out_w);
    ln_kernel<<<ROWS, 256>>>(x, ln_g, ln_b);
    mma_gemm_kernel<<<dim3(D_MODEL / BN, ROWS / BM, 3), 256, GEMM_SMEM>>>(
        0, nullptr, nullptr, nullptr);
    flash_mma_kernel<<<dim3(16, 64), 256, FLASH_SMEM>>>(kpm);
    mma_gemm_kernel<<<dim3(D_MODEL / BN, ROWS / BM, 1), 256, GEMM_SMEM>>>(
        1, out_b, x, out);
}

// round 13
// speedup vs baseline: 2.3424x; 1.0136x over previous
#include <cuda_runtime.h>
#include <cuda_bf16.h>
#include <math.h>
#include <cstdint>

#define D_MODEL 1024
#define SEQ     2048
#define BATCH   4
#define NH      16
#define HD      64
#define ROWS    (BATCH * SEQ)   // 8192

// ---------------------------------------------------------------------------
// Device-global scratch (no runtime allocation allowed)
// ---------------------------------------------------------------------------
__device__ float g_emb[SEQ * HD];
__device__ __nv_bfloat16 g_qh[ROWS * D_MODEL];   // Q (rot, pre-scaled) hi  [b,h,s,d]
__device__ __nv_bfloat16 g_ql[ROWS * D_MODEL];   // lo
__device__ __nv_bfloat16 g_kh[ROWS * D_MODEL];   // K (rot) hi             [b,h,s,d]
__device__ __nv_bfloat16 g_kl[ROWS * D_MODEL];   // lo
__device__ __nv_bfloat16 g_vth[ROWS * D_MODEL];  // V hi TRANSPOSED        [b,h,d,s]
__device__ __nv_bfloat16 g_vtl[ROWS * D_MODEL];  // lo
__device__ __nv_bfloat16 g_xh[ROWS * D_MODEL];   // ln(x) hi
__device__ __nv_bfloat16 g_xl[ROWS * D_MODEL];   // ln(x) lo
__device__ __nv_bfloat16 g_ah[ROWS * D_MODEL];   // attention out hi
__device__ __nv_bfloat16 g_al[ROWS * D_MODEL];   // attention out lo
__device__ __nv_bfloat16 g_wh[4 * D_MODEL * D_MODEL];  // q,k,v,out weights hi
__device__ __nv_bfloat16 g_wl[4 * D_MODEL * D_MODEL];  // lo

// ---------------------------------------------------------------------------
// PTX helpers: ldmatrix / mma.sync bf16 / cp.async (all baseline sm_80+ ISA)
// ---------------------------------------------------------------------------
__device__ __forceinline__ uint32_t smem_to_u32(const void* smem_ptr) {
    uint32_t addr;
    asm("{ .reg .u64 tmp; cvta.to.shared.u64 tmp, %1; cvt.u32.u64 %0, tmp; }"
        : "=r"(addr) : "l"(smem_ptr));
    return addr;
}
__device__ __forceinline__ void ldm_x4(uint32_t* r, uint32_t addr) {
    asm volatile("ldmatrix.sync.aligned.m8n8.x4.shared.b16 {%0,%1,%2,%3}, [%4];"
        : "=r"(r[0]), "=r"(r[1]), "=r"(r[2]), "=r"(r[3]) : "r"(addr));
}
__device__ __forceinline__ void mma_bf16(float* c, const uint32_t* a, const uint32_t* b) {
    asm volatile(
        "mma.sync.aligned.m16n8k16.row.col.f32.bf16.bf16.f32 "
        "{%0,%1,%2,%3}, {%4,%5,%6,%7}, {%8,%9}, {%0,%1,%2,%3};"
        : "+f"(c[0]), "+f"(c[1]), "+f"(c[2]), "+f"(c[3])
        : "r"(a[0]), "r"(a[1]), "r"(a[2]), "r"(a[3]), "r"(b[0]), "r"(b[1]));
}
__device__ __forceinline__ void cp_async16(uint32_t smem, const void* gptr) {
    asm volatile("cp.async.cg.shared.global [%0], [%1], 16;"
        :: "r"(smem), "l"(gptr));
}
#define CP_COMMIT() asm volatile("cp.async.commit_group;" ::: "memory")
#define CP_WAIT0()  asm volatile("cp.async.wait_group 0;" ::: "memory")

__device__ __forceinline__ uint32_t pack_bf16x2(float lo, float hi) {
    __nv_bfloat162 p(__float2bfloat16(lo), __float2bfloat16(hi));
    return *(uint32_t*)&p;
}

// ---------------------------------------------------------------------------
// Rotary emb table (double precision — args reach ~2048 rad)
// ---------------------------------------------------------------------------
__global__ __launch_bounds__(256) void emb_kernel() {
    int idx = blockIdx.x * 256 + threadIdx.x;   // 0 .. SEQ*HD-1
    int s = idx >> 6;
    int d = idx & 63;
    int i = d & 31;
    double f = exp(-log(10000.0) * (double)i / 32.0);
    double a = (double)s * f;
    g_emb[idx] = (d < 32) ? (float)sin(a) : (float)cos(a);
}

// ---------------------------------------------------------------------------
// Weight hi/lo bf16 split: 4 x 1024x1024
// ---------------------------------------------------------------------------
__global__ __launch_bounds__(256) void wconv_kernel(const float* __restrict__ q,
                                                    const float* __restrict__ k,
                                                    const float* __restrict__ v,
                                                    const float* __restrict__ o) {
    int i = blockIdx.x * 256 + threadIdx.x;   // 0 .. 4M-1
    int m = i >> 20;
    const float* src = (m == 0) ? q : (m == 1) ? k : (m == 2) ? v : o;
    float val = src[i & 0xFFFFF];
    __nv_bfloat16 h = __float2bfloat16(val);
    g_wh[i] = h;
    g_wl[i] = __float2bfloat16(val - __bfloat162float(h));
}

// ---------------------------------------------------------------------------
// LayerNorm fused with bf16 hi/lo split output
// ---------------------------------------------------------------------------
__global__ __launch_bounds__(256) void ln_kernel(const float* __restrict__ x,
                                                 const float* __restrict__ g,
                                                 const float* __restrict__ b) {
    int row = blockIdx.x;
    int tid = threadIdx.x;
    const float* xr = x + (size_t)row * D_MODEL;
    float4 v = *(const float4*)(xr + tid * 4);
    float s1 = v.x + v.y + v.z + v.w;
    float s2 = v.x * v.x + v.y * v.y + v.z * v.z + v.w * v.w;
#pragma unroll
    for (int off = 16; off; off >>= 1) {
        s1 += __shfl_xor_sync(0xffffffffu, s1, off);
        s2 += __shfl_xor_sync(0xffffffffu, s2, off);
    }
    __shared__ float r1[8], r2[8];
    int w = tid >> 5, lane = tid & 31;
    if (lane == 0) { r1[w] = s1; r2[w] = s2; }
    __syncthreads();
    float t1 = 0.f, t2 = 0.f;
#pragma unroll
    for (int i = 0; i < 8; i++) { t1 += r1[i]; t2 += r2[i]; }
    float mu   = t1 * (1.f / D_MODEL);
    float var  = t2 * (1.f / D_MODEL) - mu * mu;
    float rstd = rsqrtf(var + 1e-5f);
    float4 gv = *(const float4*)(g + tid * 4);
    float4 bv = *(const float4*)(b + tid * 4);
    float o0 = (v.x - mu) * rstd * gv.x + bv.x;
    float o1 = (v.y - mu) * rstd * gv.y + bv.y;
    float o2 = (v.z - mu) * rstd * gv.z + bv.z;
    float o3 = (v.w - mu) * rstd * gv.w + bv.w;
    size_t base = (size_t)row * D_MODEL + tid * 4;
    __nv_bfloat16 h0 = __float2bfloat16(o0), h1 = __float2bfloat16(o1);
    __nv_bfloat16 h2 = __float2bfloat16(o2), h3 = __float2bfloat16(o3);
    *(__nv_bfloat162*)&g_xh[base]     = __nv_bfloat162(h0, h1);
    *(__nv_bfloat162*)&g_xh[base + 2] = __nv_bfloat162(h2, h3);
    *(__nv_bfloat162*)&g_xl[base] =
        __nv_bfloat162(__float2bfloat16(o0 - __bfloat162float(h0)),
                       __float2bfloat16(o1 - __bfloat162float(h1)));
    *(__nv_bfloat162*)&g_xl[base + 2] =
        __nv_bfloat162(__float2bfloat16(o2 - __bfloat162float(h2)),
                       __float2bfloat16(o3 - __bfloat162float(h3)));
}

// ---------------------------------------------------------------------------
// HMMA bf16-split GEMM:  C[128x128 tile] = A[M,1024] @ W[N,1024]^T
// Single barrier per chunk: wait0 -> sync -> prefetch(c+1) -> compute(c).
// mode 0: QKV (+rot, q scaled, v transposed); mode 1: out-proj.
// ---------------------------------------------------------------------------
#define BM 128
#define BN 128
#define BK 32
#define ROWB 80                          // padded smem row bytes (32 bf16 + pad)
#define MAT_BYTES (128 * ROWB)           // 10240
#define BUF_BYTES (4 * MAT_BYTES)        // Ah, Al, Wh, Wl
#define GEMM_SMEM (2 * BUF_BYTES)        // 81920

__global__ __launch_bounds__(256) void mma_gemm_kernel(int mode,
                                                       const float* __restrict__ bias,
                                                       const float* __restrict__ xres,
                                                       float* __restrict__ outp) {
    extern __shared__ char dsm[];
    uint32_t s0 = smem_to_u32(dsm);
    int tid = threadIdx.x, lane = tid & 31, wid = tid >> 5;
    int wm = wid >> 2, wn = wid & 3;
    int z = blockIdx.z;
    int row0 = blockIdx.y * BM;
    int col0 = blockIdx.x * BN;

    const __nv_bfloat16* Ah = (mode == 0) ? g_xh : g_ah;
    const __nv_bfloat16* Al = (mode == 0) ? g_xl : g_al;
    int widx = (mode == 0) ? z : 3;
    const __nv_bfloat16* Wh = g_wh + (size_t)widx * D_MODEL * D_MODEL;
    const __nv_bfloat16* Wl = g_wl + (size_t)widx * D_MODEL * D_MODEL;

    float C[4][4][4];
#pragma unroll
    for (int mi = 0; mi < 4; mi++)
#pragma unroll
        for (int nj = 0; nj < 4; nj++)
#pragma unroll
            for (int q = 0; q < 4; q++) C[mi][nj][q] = 0.f;

    // Per-thread load addressing (2 rows per matrix; fully unrolled, no arrays)
    int lr_ = tid >> 2, lcu = tid & 3;            // row 0..63, 16B unit 0..3
    uint32_t sA = (uint32_t)(lr_ * ROWB + lcu * 16);
    size_t gAoff = (size_t)lr_ * D_MODEL + lcu * 8;

    auto load_chunk = [&](int c, int bi) {
        int kt = c * BK;
        uint32_t sb = s0 + bi * BUF_BYTES;
        const __nv_bfloat16* pAh = Ah + (size_t)row0 * D_MODEL + kt + gAoff;
        const __nv_bfloat16* pAl = Al + (size_t)row0 * D_MODEL + kt + gAoff;
        const __nv_bfloat16* pWh = Wh + (size_t)col0 * D_MODEL + kt + gAoff;
        const __nv_bfloat16* pWl = Wl + (size_t)col0 * D_MODEL + kt + gAoff;
        const size_t rstep = (size_t)64 * D_MODEL;
        cp_async16(sb + sA,                                   pAh);
        cp_async16(sb + sA + 64 * ROWB,                       pAh + rstep);
        cp_async16(sb + MAT_BYTES + sA,                       pAl);
        cp_async16(sb + MAT_BYTES + sA + 64 * ROWB,           pAl + rstep);
        cp_async16(sb + 2 * MAT_BYTES + sA,                   pWh);
        cp_async16(sb + 2 * MAT_BYTES + sA + 64 * ROWB,       pWh + rstep);
        cp_async16(sb + 3 * MAT_BYTES + sA,                   pWl);
        cp_async16(sb + 3 * MAT_BYTES + sA + 64 * ROWB,       pWl + rstep);
    };

    int amat = lane >> 3;                       // 0..3
    int mrow = (amat & 1) * 8 + (lane & 7);     // row offset within 16-row tile
    int mcu  = amat >> 1;                       // k-unit (16B) offset

    load_chunk(0, 0);
    CP_COMMIT();

    for (int c = 0; c < 32; c++) {
        int bi = c & 1;
        CP_WAIT0();
        __syncthreads();
        if (c < 32 - 1) { load_chunk(c + 1, bi ^ 1); CP_COMMIT(); }

        uint32_t ahB = s0 + bi * BUF_BYTES;
        uint32_t alB = ahB + MAT_BYTES;
        uint32_t whB = ahB + 2 * MAT_BYTES;
        uint32_t wlB = ahB + 3 * MAT_BYTES;

#pragma unroll
        for (int ks = 0; ks < 2; ks++) {
            int k0u = ks * 2;
            uint32_t fa_h[4][4], fa_l[4][4];
#pragma unroll
            for (int mi = 0; mi < 4; mi++) {
                uint32_t off = (uint32_t)((wm * 64 + mi * 16 + mrow) * ROWB +
                                          (k0u + mcu) * 16);
                ldm_x4(fa_h[mi], ahB + off);
                ldm_x4(fa_l[mi], alB + off);
            }
            uint32_t fb_h[2][4], fb_l[2][4];
#pragma unroll
            for (int hf = 0; hf < 2; hf++) {
                uint32_t off = (uint32_t)((wn * 32 + hf * 16 + mrow) * ROWB +
                                          (k0u + mcu) * 16);
                ldm_x4(fb_h[hf], whB + off);
                ldm_x4(fb_l[hf], wlB + off);
            }
            // Pass 1: Ah * Wh
#pragma unroll
            for (int mi = 0; mi < 4; mi++)
#pragma unroll
                for (int nj = 0; nj < 4; nj++) {
                    int hf = nj >> 1, lo = nj & 1;
                    uint32_t bv[2] = {fb_h[hf][lo], fb_h[hf][lo + 2]};
                    mma_bf16(C[mi][nj], fa_h[mi], bv);
                }
            // Pass 2: Ah * Wl
#pragma unroll
            for (int mi = 0; mi < 4; mi++)
#pragma unroll
                for (int nj = 0; nj < 4; nj++) {
                    int hf = nj >> 1, lo = nj & 1;
                    uint32_t bv[2] = {fb_l[hf][lo], fb_l[hf][lo + 2]};
                    mma_bf16(C[mi][nj], fa_h[mi], bv);
                }
            // Pass 3: Al * Wh
#pragma unroll
            for (int mi = 0; mi < 4; mi++)
#pragma unroll
                for (int nj = 0; nj < 4; nj++) {
                    int hf = nj >> 1, lo = nj & 1;
                    uint32_t bv[2] = {fb_h[hf][lo], fb_h[hf][lo + 2]};
                    mma_bf16(C[mi][nj], fa_l[mi], bv);
                }
        }
    }

    // Epilogue
    int g = lane >> 2, t = lane & 3;
#pragma unroll
    for (int mi = 0; mi < 4; mi++) {
#pragma unroll
        for (int nj = 0; nj < 4; nj++) {
            int cbase = col0 + wn * 32 + nj * 8 + t * 2;
#pragma unroll
            for (int rr = 0; rr < 2; rr++) {
                int r = row0 + wm * 64 + mi * 16 + g + rr * 8;
                float vx = C[mi][nj][rr * 2 + 0];
                float vy = C[mi][nj][rr * 2 + 1];
                if (mode == 0) {
                    int b = r >> 11, s = r & 2047, h = cbase >> 6, dd = cbase & 63;
                    if (z < 2) {
                        vx *= g_emb[s * HD + dd];
                        vy *= g_emb[s * HD + dd + 1];
                        if (z == 0) { vx *= 0.125f; vy *= 0.125f; }
                    }
                    __nv_bfloat16 hx = __float2bfloat16(vx);
                    __nv_bfloat16 hy = __float2bfloat16(vy);
                    __nv_bfloat16 lx = __float2bfloat16(vx - __bfloat162float(hx));
                    __nv_bfloat16 ly = __float2bfloat16(vy - __bfloat162float(hy));
                    if (z == 2) {
                        // transposed V: [b,h,d,s]
                        size_t tb = ((size_t)(b * NH + h) * HD + dd) * SEQ + s;
                        g_vth[tb] = hx;        g_vtl[tb] = lx;
                        g_vth[tb + SEQ] = hy;  g_vtl[tb + SEQ] = ly;
                    } else {
                        size_t ib = ((size_t)(b * NH + h) * SEQ + s) * HD + dd;
                        __nv_bfloat16* dh = (z == 0) ? g_qh : g_kh;
                        __nv_bfloat16* dl = (z == 0) ? g_ql : g_kl;
                        *(__nv_bfloat162*)&dh[ib] = __nv_bfloat162(hx, hy);
                        *(__nv_bfloat162*)&dl[ib] = __nv_bfloat162(lx, ly);
                    }
                } else {
                    float2 bv = *(const float2*)&bias[cbase];
                    float2 xv = *(const float2*)&xres[(size_t)r * D_MODEL + cbase];
                    float2 v;
                    v.x = vx + bv.x + xv.x;
                    v.y = vy + bv.y + xv.y;
                    *(float2*)&outp[(size_t)r * D_MODEL + cbase] = v;
                }
            }
        }
    }
}

// ---------------------------------------------------------------------------
// HMMA flash attention: 128 q-rows/CTA, 64-key tiles, 8 warps (16 q-rows each).
// Double-buffered K/V/mask smem; one __syncthreads per kt iteration.
// Softmax exp/pack interleaved per-ks with the PV mma (pipe stays fed).
// Heavy-first CTA order (qt reversed) to shrink the causal tail wave.
// ---------------------------------------------------------------------------
#define FP 144                            // smem row pitch bytes (64 bf16 + 8 pad)
#define FQH_B 0
#define FQL_B (128 * FP)                  // 18432
#define KV0_B (2 * 128 * FP)              // 36864
#define KVSTAGE_B (4 * 64 * FP)           // 36864
#define KH_OFF 0
#define KL_OFF (64 * FP)
#define VH_OFF (2 * 64 * FP)
#define VL_OFF (3 * 64 * FP)
#define FMS_B (KV0_B + 2 * KVSTAGE_B)     // 110592
#define FLASH_SMEM (FMS_B + 2 * 64 * 4)   // 111104

__global__ __launch_bounds__(256) void flash_mma_kernel(const unsigned char* __restrict__ kpm) {
    extern __shared__ char fsm[];
    uint32_t s0 = smem_to_u32(fsm);
    float* Ms = (float*)(fsm + FMS_B);

    int tid = threadIdx.x, lane = tid & 31, wid = tid >> 5;
    int qt = (int)gridDim.x - 1 - (int)blockIdx.x;   // heavy tiles first
    int bh = blockIdx.y;            // 0..63
    int b = bh >> 4, h = bh & 15;
    int q0 = qt * 128;

    int g = lane >> 2, t4 = lane & 3;
    int amat = lane >> 3;
    int mrow = (amat & 1) * 8 + (lane & 7);
    int mcu  = amat >> 1;

    auto load_kv = [&](int kt, int stage) {
        int k0 = kt * 64;
        uint32_t kb = s0 + KV0_B + stage * KVSTAGE_B;
#pragma unroll
        for (int t = 0; t < 2; t++) {
            int u = tid + t * 256;      // 0..511
            int r = u >> 3, cu = u & 7;
            size_t ki = ((size_t)bh * SEQ + k0 + r) * HD + cu * 8;
            size_t vi = ((size_t)bh * HD + r) * SEQ + k0 + cu * 8;
            cp_async16(kb + KH_OFF + r * FP + cu * 16, g_kh + ki);
            cp_async16(kb + KL_OFF + r * FP + cu * 16, g_kl + ki);
            cp_async16(kb + VH_OFF + r * FP + cu * 16, g_vth + vi);
            cp_async16(kb + VL_OFF + r * FP + cu * 16, g_vtl + vi);
        }
    };

    // Initial: Q tile (hi+lo) + KV stage 0 + mask slot 0
#pragma unroll
    for (int t = 0; t < 4; t++) {
        int u = tid + t * 256;          // 0..1023
        int r = u >> 3, cu = u & 7;
        size_t gi = ((size_t)bh * SEQ + q0 + r) * HD + cu * 8;
        cp_async16(s0 + FQH_B + r * FP + cu * 16, g_qh + gi);
        cp_async16(s0 + FQL_B + r * FP + cu * 16, g_ql + gi);
    }
    load_kv(0, 0);
    if (tid < 64) Ms[tid] = kpm[b * SEQ + tid] ? -1e30f : 0.f;
    CP_COMMIT();

    float mr[2] = {-INFINITY, -INFINITY};
    float lr[2] = {0.f, 0.f};
    float O[8][4];
#pragma unroll
    for (int j = 0; j < 8; j++)
#pragma unroll
        for (int q = 0; q < 4; q++) O[j][q] = 0.f;

    int rowg = q0 + wid * 16 + g;       // this thread's first q row

    int ktmax = (q0 + 127) >> 6;
    for (int kt = 0; kt <= ktmax; kt++) {
        int bi = kt & 1;
        int k0 = kt * 64;
        CP_WAIT0();
        __syncthreads();
        if (kt < ktmax) {
            load_kv(kt + 1, bi ^ 1);
            CP_COMMIT();
            if (tid < 64)
                Ms[(bi ^ 1) * 64 + tid] =
                    kpm[b * SEQ + (kt + 1) * 64 + tid] ? -1e30f : 0.f;
        }
        uint32_t kvb = s0 + KV0_B + bi * KVSTAGE_B;
        float* Msl = Ms + bi * 64;

        // ---- S = Q K^T (3-term, pass-separated) ----
        float S[8][4];
#pragma unroll
        for (int j = 0; j < 8; j++)
#pragma unroll
            for (int q = 0; q < 4; q++) S[j][q] = 0.f;

#pragma unroll
        for (int ks = 0; ks < 4; ks++) {
            uint32_t qh[4], ql[4];
            uint32_t qoff = (uint32_t)((wid * 16 + mrow) * FP + ks * 32 + mcu * 16);
            ldm_x4(qh, s0 + FQH_B + qoff);
            ldm_x4(ql, s0 + FQL_B + qoff);
            uint32_t kh[4][4], kl[4][4];
#pragma unroll
            for (int grp = 0; grp < 4; grp++) {
                uint32_t koff = (uint32_t)((grp * 16 + mrow) * FP + ks * 32 + mcu * 16);
                ldm_x4(kh[grp], kvb + KH_OFF + koff);
                ldm_x4(kl[grp], kvb + KL_OFF + koff);
            }
#pragma unroll
            for (int j = 0; j < 8; j++) {
                int grp = j >> 1, lo = j & 1;
                uint32_t bv[2] = {kh[grp][lo], kh[grp][lo + 2]};
                mma_bf16(S[j], qh, bv);
            }
#pragma unroll
            for (int j = 0; j < 8; j++) {
                int grp = j >> 1, lo = j & 1;
                uint32_t bv[2] = {kl[grp][lo], kl[grp][lo + 2]};
                mma_bf16(S[j], qh, bv);
            }
#pragma unroll
            for (int j = 0; j < 8; j++) {
                int grp = j >> 1, lo = j & 1;
                uint32_t bv[2] = {kh[grp][lo], kh[grp][lo + 2]};
                mma_bf16(S[j], ql, bv);
            }
        }

        // ---- mask + row max (no MUFU) ----
        bool needc = (k0 + 63 > q0);
#pragma unroll
        for (int j = 0; j < 8; j++) {
            int c0 = 8 * j + t4 * 2;
            float m0 = Msl[c0], m1 = Msl[c0 + 1];
            float s0v = S[j][0] + m0, s1v = S[j][1] + m1;
            float s2v = S[j][2] + m0, s3v = S[j][3] + m1;
            if (needc) {
                int kc0 = k0 + c0;
                if (kc0 > rowg)          s0v = -1e30f;
                if (kc0 + 1 > rowg)      s1v = -1e30f;
                if (kc0 > rowg + 8)      s2v = -1e30f;
                if (kc0 + 1 > rowg + 8)  s3v = -1e30f;
            }
            S[j][0] = s0v; S[j][1] = s1v; S[j][2] = s2v; S[j][3] = s3v;
        }
        float mt0 = -1e30f, mt1 = -1e30f;
#pragma unroll
        for (int j = 0; j < 8; j++) {
            mt0 = fmaxf(mt0, fmaxf(S[j][0], S[j][1]));
            mt1 = fmaxf(mt1, fmaxf(S[j][2], S[j][3]));
        }
        mt0 = fmaxf(mt0, __shfl_xor_sync(0xffffffffu, mt0, 1));
        mt0 = fmaxf(mt0, __shfl_xor_sync(0xffffffffu, mt0, 2));
        mt1 = fmaxf(mt1, __shfl_xor_sync(0xffffffffu, mt1, 1));
        mt1 = fmaxf(mt1, __shfl_xor_sync(0xffffffffu, mt1, 2));
        float mn0 = fmaxf(mr[0], mt0), mn1 = fmaxf(mr[1], mt1);
        float corr0 = __expf(mr[0] - mn0), corr1 = __expf(mr[1] - mn1);
        mr[0] = mn0; mr[1] = mn1;
#pragma unroll
        for (int j = 0; j < 8; j++) {
            O[j][0] *= corr0; O[j][1] *= corr0;
            O[j][2] *= corr1; O[j][3] *= corr1;
        }

        // ---- interleaved: exp/pack of chunk ks + PV mma of chunk ks ----
        float rs0 = 0.f, rs1 = 0.f;
#pragma unroll
        for (int ks = 0; ks < 4; ks++) {
            int j0 = 2 * ks, j1 = 2 * ks + 1;
            // exp just the 16 P-columns this PV chunk needs
            float a0 = __expf(S[j0][0] - mn0), a1 = __expf(S[j0][1] - mn0);
            float a2 = __expf(S[j0][2] - mn1), a3 = __expf(S[j0][3] - mn1);
            float b0 = __expf(S[j1][0] - mn0), b1 = __expf(S[j1][1] - mn0);
            float b2 = __expf(S[j1][2] - mn1), b3 = __expf(S[j1][3] - mn1);
            rs0 += a0 + a1 + b0 + b1;
            rs1 += a2 + a3 + b2 + b3;
            uint32_t pah[4], pal[4];
            pah[0] = pack_bf16x2(a0, a1);
            pah[1] = pack_bf16x2(a2, a3);
            pah[2] = pack_bf16x2(b0, b1);
            pah[3] = pack_bf16x2(b2, b3);
            pal[0] = pack_bf16x2(a0 - __bfloat162float(__float2bfloat16(a0)),
                                 a1 - __bfloat162float(__float2bfloat16(a1)));
            pal[1] = pack_bf16x2(a2 - __bfloat162float(__float2bfloat16(a2)),
                                 a3 - __bfloat162float(__float2bfloat16(a3)));
            pal[2] = pack_bf16x2(b0 - __bfloat162float(__float2bfloat16(b0)),
                                 b1 - __bfloat162float(__float2bfloat16(b1)));
            pal[3] = pack_bf16x2(b2 - __bfloat162float(__float2bfloat16(b2)),
                                 b3 - __bfloat162float(__float2bfloat16(b3)));
            uint32_t vh[4][4], vl[4][4];
#pragma unroll
            for (int grp = 0; grp < 4; grp++) {
                uint32_t voff = (uint32_t)((grp * 16 + mrow) * FP + ks * 32 + mcu * 16);
                ldm_x4(vh[grp], kvb + VH_OFF + voff);
                ldm_x4(vl[grp], kvb + VL_OFF + voff);
            }
#pragma unroll
            for (int jd = 0; jd < 8; jd++) {
                int grp = jd >> 1, lo = jd & 1;
                uint32_t bv[2] = {vh[grp][lo], vh[grp][lo + 2]};
                mma_bf16(O[jd], pah, bv);
            }
#pragma unroll
            for (int jd = 0; jd < 8; jd++) {
                int grp = jd >> 1, lo = jd & 1;
                uint32_t bv[2] = {vl[grp][lo], vl[grp][lo + 2]};
                mma_bf16(O[jd], pah, bv);
            }
#pragma unroll
            for (int jd = 0; jd < 8; jd++) {
                int grp = jd >> 1, lo = jd & 1;
                uint32_t bv[2] = {vh[grp][lo], vh[grp][lo + 2]};
                mma_bf16(O[jd], pal, bv);
            }
        }

        // row-sum reductions off the critical path
        rs0 += __shfl_xor_sync(0xffffffffu, rs0, 1);
        rs0 += __shfl_xor_sync(0xffffffffu, rs0, 2);
        rs1 += __shfl_xor_sync(0xffffffffu, rs1, 1);
        rs1 += __shfl_xor_sync(0xffffffffu, rs1, 2);
        lr[0] = lr[0] * corr0 + rs0;
        lr[1] = lr[1] * corr1 + rs1;
    }

    // ---- epilogue: normalize, write bf16 hi/lo to [B,S,D] for out-proj ----
    float inv0 = 1.f / lr[0], inv1 = 1.f / lr[1];
#pragma unroll
    for (int j = 0; j < 8; j++) {
        int dd = h * HD + 8 * j + t4 * 2;
        {
            float vx = O[j][0] * inv0, vy = O[j][1] * inv0;
            size_t idx = (size_t)(b * SEQ + rowg) * D_MODEL + dd;
            __nv_bfloat16 hx = __float2bfloat16(vx), hy = __float2bfloat16(vy);
            *(__nv_bfloat162*)&g_ah[idx] = __nv_bfloat162(hx, hy);
            *(__nv_bfloat162*)&g_al[idx] =
                __nv_bfloat162(__float2bfloat16(vx - __bfloat162float(hx)),
                               __float2bfloat16(vy - __bfloat162float(hy)));
        }
        {
            float vx = O[j][2] * inv1, vy = O[j][3] * inv1;
            size_t idx = (size_t)(b * SEQ + rowg + 8) * D_MODEL + dd;
            __nv_bfloat16 hx = __float2bfloat16(vx), hy = __float2bfloat16(vy);
            *(__nv_bfloat162*)&g_ah[idx] = __nv_bfloat162(hx, hy);
            *(__nv_bfloat162*)&g_al[idx] =
                __nv_bfloat162(__float2bfloat16(vx - __bfloat162float(hx)),
                               __float2bfloat16(vy - __bfloat162float(hy)));
        }
    }
}

// ---------------------------------------------------------------------------
extern "C" void kernel_launch(void* const* d_in, const int* in_sizes, int n_in,
                              void* d_out, int out_size) {
    const float* x            = (const float*)d_in[0];
    const unsigned char* kpm  = (const unsigned char*)d_in[1];
    const float* q_w          = (const float*)d_in[2];
    const float* k_w          = (const float*)d_in[3];
    const float* v_w          = (const float*)d_in[4];
    const float* out_w        = (const float*)d_in[5];
    const float* out_b        = (const float*)d_in[6];
    const float* ln_g         = (const float*)d_in[7];
    const float* ln_b         = (const float*)d_in[8];
    float* out = (float*)d_out;

    cudaFuncSetAttribute(flash_mma_kernel, cudaFuncAttributeMaxDynamicSharedMemorySize, FLASH_SMEM);
    cudaFuncSetAttribute(mma_gemm_kernel, cudaFuncAttributeMaxDynamicSharedMemorySize, GEMM_SMEM);

    emb_kernel<<<(SEQ * HD) / 256, 256>>>();
    wconv_kernel<<<(4 * D_MODEL * D_MODEL) / 256, 256>>>(q_w, k_w, v_w, out_w);
    ln_kernel<<<ROWS, 256>>>(x, ln_g, ln_b);
    mma_gemm_kernel<<<dim3(D_MODEL / BN, ROWS / BM, 3), 256, GEMM_SMEM>>>(
        0, nullptr, nullptr, nullptr);
    flash_mma_kernel<<<dim3(16, 64), 256, FLASH_SMEM>>>(kpm);
    mma_gemm_kernel<<<dim3(D_MODEL / BN, ROWS / BM, 1), 256, GEMM_SMEM>>>(
        1, out_b, x, out);
}